// round 9
// baseline (speedup 1.0000x reference)
#include <cuda_runtime.h>
#include <cuda_bf16.h>
#include <cstdint>

#define D_MODEL 1024
#define NH 16
#define HD 64
#define CHUNK 256
#define WIN 64
#define BATCH 4
#define SEQ 8192
#define NCHUNK (SEQ / CHUNK)
#define ROWS (BATCH * SEQ)

// ---------------- scratch (__device__ globals; no allocs allowed) ----------
__device__ float g_q[ROWS * D_MODEL];
__device__ float g_k[ROWS * D_MODEL];
__device__ float g_v[ROWS * D_MODEL];
__device__ __nv_bfloat16 g_x_hi[ROWS * D_MODEL];
__device__ __nv_bfloat16 g_x_lo[ROWS * D_MODEL];
__device__ __nv_bfloat16 g_att_hi[ROWS * D_MODEL];
__device__ __nv_bfloat16 g_att_lo[ROWS * D_MODEL];
// 4 transposed weights (q,k,v,o), hi/lo limbs, each [N=1024][K=1024] (K-major)
__device__ __nv_bfloat16 g_wt_hi[4 * D_MODEL * D_MODEL];
__device__ __nv_bfloat16 g_wt_lo[4 * D_MODEL * D_MODEL];

// ---------------------------------------------------------------------------
// helpers
// ---------------------------------------------------------------------------
__device__ __forceinline__ uint32_t smem_u32(const void* p) {
    uint32_t a;
    asm("{ .reg .u64 t; cvta.to.shared.u64 t, %1; cvt.u32.u64 %0, t; }"
        : "=r"(a) : "l"(p));
    return a;
}

__device__ __forceinline__ void cp_async16(uint32_t dst, const void* src) {
    asm volatile("cp.async.cg.shared.global [%0], [%1], 16;"
                 :: "r"(dst), "l"(src) : "memory");
}
__device__ __forceinline__ void cp_commit() {
    asm volatile("cp.async.commit_group;" ::: "memory");
}
__device__ __forceinline__ void cp_wait1() {
    asm volatile("cp.async.wait_group 1;" ::: "memory");
}

__device__ __forceinline__ void ldsm_x4(uint32_t* r, uint32_t addr) {
    asm volatile("ldmatrix.sync.aligned.m8n8.x4.shared.b16 {%0,%1,%2,%3}, [%4];"
                 : "=r"(r[0]), "=r"(r[1]), "=r"(r[2]), "=r"(r[3]) : "r"(addr));
}

__device__ __forceinline__ void mma16816(float* c, const uint32_t* a, const uint32_t* b) {
    asm volatile(
        "mma.sync.aligned.m16n8k16.row.col.f32.bf16.bf16.f32 "
        "{%0,%1,%2,%3}, {%4,%5,%6,%7}, {%8,%9}, {%0,%1,%2,%3};"
        : "+f"(c[0]), "+f"(c[1]), "+f"(c[2]), "+f"(c[3])
        : "r"(a[0]), "r"(a[1]), "r"(a[2]), "r"(a[3]), "r"(b[0]), "r"(b[1]));
}

// ---- packed f32x2 ops (FFMA2 path, PTX-only per SASS_QUICKREF) ----
__device__ __forceinline__ uint64_t pack2f(float lo, float hi) {
    uint64_t r;
    asm("mov.b64 %0, {%1,%2};" : "=l"(r) : "f"(lo), "f"(hi));
    return r;
}
__device__ __forceinline__ void unpack2f(uint64_t p, float& lo, float& hi) {
    asm("mov.b64 {%0,%1}, %2;" : "=f"(lo), "=f"(hi) : "l"(p));
}
__device__ __forceinline__ void fma2(uint64_t& d, uint64_t a, uint64_t b) {
    asm("fma.rn.f32x2 %0, %1, %2, %0;" : "+l"(d) : "l"(a), "l"(b));
}
__device__ __forceinline__ uint64_t mul2(uint64_t a, uint64_t b) {
    uint64_t r;
    asm("mul.rn.f32x2 %0, %1, %2;" : "=l"(r) : "l"(a), "l"(b));
    return r;
}
__device__ __forceinline__ uint64_t add2(uint64_t a, uint64_t b) {
    uint64_t r;
    asm("add.rn.f32x2 %0, %1, %2;" : "=l"(r) : "l"(a), "l"(b));
    return r;
}
__device__ __forceinline__ void lds_v2u64(uint64_t& a, uint64_t& b, uint32_t addr) {
    asm volatile("ld.shared.v2.b64 {%0,%1}, [%2];" : "=l"(a), "=l"(b) : "r"(addr));
}

// tile geometry: 128 rows x 32 bf16 cols = 64B rows, 4x 16B chunks per row
// swizzled 16B-chunk: c' = c ^ ((r>>1)&3)
#define TILE_B 8192
#define STAGE_B (4 * TILE_B)   // Ahi, Alo, Bhi, Blo
#define NSTAGE 3
#define GEMM_SMEM (NSTAGE * STAGE_B)  // 98304
#define KIT 32                 // 1024 / 32

__device__ __forceinline__ uint32_t sw_addr(uint32_t tile_base, int r, int c) {
    return tile_base + r * 64 + ((c ^ ((r >> 1) & 3)) << 4);
}

// ---------------------------------------------------------------------------
// Split fp32 -> bf16 hi/lo limbs
// ---------------------------------------------------------------------------
__global__ __launch_bounds__(256) void split_kernel(
    const float* __restrict__ in, __nv_bfloat16* __restrict__ hi,
    __nv_bfloat16* __restrict__ lo, int n4)
{
    int i = blockIdx.x * blockDim.x + threadIdx.x;
    if (i >= n4) return;
    float4 x = ((const float4*)in)[i];
    float v[4] = {x.x, x.y, x.z, x.w};
    __nv_bfloat16 h[4], l[4];
#pragma unroll
    for (int j = 0; j < 4; j++) {
        h[j] = __float2bfloat16(v[j]);
        l[j] = __float2bfloat16(v[j] - __bfloat162float(h[j]));
    }
    *(uint2*)(hi + 4 * (size_t)i) = *(uint2*)h;
    *(uint2*)(lo + 4 * (size_t)i) = *(uint2*)l;
}

// Fused weight transpose + split for all 4 weights (grid.z selects W)
__global__ __launch_bounds__(256) void wsplit4_kernel(
    const float* __restrict__ W0, const float* __restrict__ W1,
    const float* __restrict__ W2, const float* __restrict__ W3,
    __nv_bfloat16* __restrict__ hiT, __nv_bfloat16* __restrict__ loT)
{
    __shared__ float tile[32][33];
    const int z = blockIdx.z;
    const float* W = (z == 0) ? W0 : (z == 1) ? W1 : (z == 2) ? W2 : W3;
    const size_t off = (size_t)z * D_MODEL * D_MODEL;
    int bx = blockIdx.x * 32, by = blockIdx.y * 32;
    int tx = threadIdx.x, ty = threadIdx.y;  // 32x8
#pragma unroll
    for (int r = ty; r < 32; r += 8)
        tile[r][tx] = W[(size_t)(by + r) * D_MODEL + bx + tx];
    __syncthreads();
#pragma unroll
    for (int r = ty; r < 32; r += 8) {
        float v = tile[tx][r];  // = W[(by+tx)*D + bx+r]
        __nv_bfloat16 h = __float2bfloat16(v);
        size_t o = off + (size_t)(bx + r) * D_MODEL + by + tx;
        hiT[o] = h;
        loT[o] = __float2bfloat16(v - __bfloat162float(h));
    }
}

// ---------------------------------------------------------------------------
// bf16-split GEMM via mma.sync, multi-output variant.
// B spans blockIdx.x*128 rows of the (possibly concatenated) weight matrix;
// output tensor = C[blockIdx.x >> 3], column = blockIdx.x & 7.
// CTA 128x128, BK=32, 3-stage cp.async pipeline, 8 warps, 2 CTAs/SM.
// ---------------------------------------------------------------------------
__global__ __launch_bounds__(256, 2) void gemm_mma_kernel(
    const __nv_bfloat16* __restrict__ Ahi, const __nv_bfloat16* __restrict__ Alo,
    const __nv_bfloat16* __restrict__ Bhi, const __nv_bfloat16* __restrict__ Blo,
    float* __restrict__ C0, float* __restrict__ C1, float* __restrict__ C2)
{
    extern __shared__ char smem[];
    const uint32_t sbase = smem_u32(smem);
    const int tid = threadIdx.x;
    const int lane = tid & 31;
    const int wid = tid >> 5;
    const int wm = wid >> 2;        // 0..1
    const int wn = wid & 3;         // 0..3
    const int m0 = blockIdx.y * 128;
    const int nB = blockIdx.x * 128;        // row in the B (weight) matrix
    const int w = nB >> 10;
    const int col0 = nB & 1023;
    float* __restrict__ C = (w == 0) ? C0 : (w == 1) ? C1 : C2;

    const __nv_bfloat16* srcs[4] = {Ahi, Alo, Bhi, Blo};

    auto load_stage = [&](int stage, int k0) {
        uint32_t sb = sbase + stage * STAGE_B;
#pragma unroll
        for (int t = 0; t < 4; t++) {
            int row0 = (t < 2) ? m0 : nB;
            const __nv_bfloat16* s = srcs[t];
#pragma unroll
            for (int i = 0; i < 2; i++) {
                int cid = tid + i * 256;       // 0..511
                int r = cid >> 2;
                int c = cid & 3;
                const void* g = s + (size_t)(row0 + r) * D_MODEL + k0 + c * 8;
                cp_async16(sw_addr(sb + t * TILE_B, r, c), g);
            }
        }
    };

    float acc[4][4][4];
#pragma unroll
    for (int i = 0; i < 4; i++)
#pragma unroll
        for (int j = 0; j < 4; j++)
#pragma unroll
            for (int e = 0; e < 4; e++) acc[i][j][e] = 0.f;

    load_stage(0, 0);
    cp_commit();
    load_stage(1, 32);
    cp_commit();

    const int a_r = lane & 15;
    const int a_c = lane >> 4;
    const int b_r = (lane & 7) + ((lane >> 4) << 3);
    const int b_c = (lane >> 3) & 1;

    for (int it = 0; it < KIT; it++) {
        cp_wait1();
        __syncthreads();
        if (it + 2 < KIT) load_stage((it + 2) % NSTAGE, (it + 2) * 32);
        cp_commit();

        const uint32_t sb = sbase + (it % NSTAGE) * STAGE_B;
        const uint32_t tAhi = sb;
        const uint32_t tAlo = sb + TILE_B;
        const uint32_t tBhi = sb + 2 * TILE_B;
        const uint32_t tBlo = sb + 3 * TILE_B;

#pragma unroll
        for (int ks = 0; ks < 2; ks++) {
            uint32_t a[4][4], bh[4][2], bl[4][2];
#pragma unroll
            for (int mt = 0; mt < 4; mt++) {
                int r = wm * 64 + mt * 16 + a_r;
                ldsm_x4(a[mt], sw_addr(tAhi, r, ks * 2 + a_c));
            }
#pragma unroll
            for (int np = 0; np < 2; np++) {
                uint32_t t4[4];
                int r = wn * 32 + np * 16 + b_r;
                ldsm_x4(t4, sw_addr(tBhi, r, ks * 2 + b_c));
                bh[np * 2][0] = t4[0]; bh[np * 2][1] = t4[1];
                bh[np * 2 + 1][0] = t4[2]; bh[np * 2 + 1][1] = t4[3];
            }
#pragma unroll
            for (int np = 0; np < 2; np++) {
                uint32_t t4[4];
                int r = wn * 32 + np * 16 + b_r;
                ldsm_x4(t4, sw_addr(tBlo, r, ks * 2 + b_c));
                bl[np * 2][0] = t4[0]; bl[np * 2][1] = t4[1];
                bl[np * 2 + 1][0] = t4[2]; bl[np * 2 + 1][1] = t4[3];
            }
#pragma unroll
            for (int mt = 0; mt < 4; mt++)
#pragma unroll
                for (int nt = 0; nt < 4; nt++)
                    mma16816(acc[mt][nt], a[mt], bh[nt]);
#pragma unroll
            for (int mt = 0; mt < 4; mt++)
#pragma unroll
                for (int nt = 0; nt < 4; nt++)
                    mma16816(acc[mt][nt], a[mt], bl[nt]);
#pragma unroll
            for (int mt = 0; mt < 4; mt++) {
                int r = wm * 64 + mt * 16 + a_r;
                ldsm_x4(a[mt], sw_addr(tAlo, r, ks * 2 + a_c));
            }
#pragma unroll
            for (int mt = 0; mt < 4; mt++)
#pragma unroll
                for (int nt = 0; nt < 4; nt++)
                    mma16816(acc[mt][nt], a[mt], bh[nt]);
        }
    }

    const int er = lane >> 2;
    const int ec = (lane & 3) * 2;
#pragma unroll
    for (int mt = 0; mt < 4; mt++) {
#pragma unroll
        for (int nt = 0; nt < 4; nt++) {
            int row = m0 + wm * 64 + mt * 16 + er;
            int col = col0 + wn * 32 + nt * 8 + ec;
            *(float2*)(C + (size_t)row * D_MODEL + col) =
                make_float2(acc[mt][nt][0], acc[mt][nt][1]);
            *(float2*)(C + (size_t)(row + 8) * D_MODEL + col) =
                make_float2(acc[mt][nt][2], acc[mt][nt][3]);
        }
    }
}

// ---------------------------------------------------------------------------
// Banded chunk-local attention, HALF-CHUNK CTAs for 2 CTAs/SM occupancy.
// CTA = (head, chunk, half z): 128 queries, 128 threads, 1 query/thread.
// k/v buf: up to 192 rows x 64 floats, 16B chunks swizzled by (r&7)
// (lanes read consecutive rows -> distinct chunks -> conflict-free LDS.128).
// sc: 128 rows x 67 floats (odd stride -> conflict-free column access).
// Fused bf16 hi/lo output split. smem = 83,456 B -> 2 CTAs/SM.
// ---------------------------------------------------------------------------
#define ATT_SC 67
#define ATT_BUF_FLOATS (192 * 64)
#define ATT_SMEM_BYTES ((ATT_BUF_FLOATS + 128 * ATT_SC) * 4)  // 83456

__device__ __forceinline__ int att_addr(int r, int c) {  // float index, c = 16B chunk
    return r * 64 + ((c ^ (r & 7)) << 2);
}

// load rows [row0, row0+nrows) of a head-slice into buf (local rows 0..nrows)
__device__ __forceinline__ void att_load_rows(
    float* __restrict__ buf, const float* __restrict__ src, size_t base,
    int row0, int nrows, int tid)
{
    for (int idx = tid; idx < nrows * 16; idx += 128) {
        int r = idx >> 4;
        int c = idx & 15;
        float4 t = *(const float4*)(src + base + (size_t)(row0 + r) * D_MODEL + c * 4);
        *(float4*)(buf + att_addr(r, c)) = t;
    }
}

__global__ __launch_bounds__(128) void attn_kernel(
    const float* __restrict__ q, const float* __restrict__ k,
    const float* __restrict__ v,
    __nv_bfloat16* __restrict__ ohi, __nv_bfloat16* __restrict__ olo)
{
    extern __shared__ float fsmem[];
    float* buf = fsmem;                          // [<=192][64] swizzled
    float* sc  = fsmem + ATT_BUF_FLOATS;         // [128][67]
    const uint32_t sb = smem_u32(fsmem);

    const int h = blockIdx.x;
    const int n = blockIdx.y >> 1;
    const int z = blockIdx.y & 1;                // chunk half
    const int b = blockIdx.z;
    const int t = threadIdx.x;                   // 0..127
    const int qi = z * 128 + t;                  // query row within chunk

    const size_t base = ((size_t)(b * SEQ + n * CHUNK)) * D_MODEL + h * HD;
    const int krow0 = z ? 64 : 0;                // first key row staged
    const int nk = z ? 192 : 128;                // rows staged
    const int roff = z ? t : (t - 64);           // local key row = roff + ju
    const bool full = (z != 0);                  // z=1: whole band valid

    // ---- stage this half's q rows; pull own row into packed regs ----
    att_load_rows(buf, q, base, z * 128, 128, t);
    __syncthreads();
    uint64_t qp[32];
    {
        const uint64_t scale2 = pack2f(0.125f, 0.125f);
#pragma unroll
        for (int c = 0; c < 16; c++) {
            uint64_t a, bq;
            lds_v2u64(a, bq, sb + 4 * att_addr(t, c));
            qp[2 * c] = mul2(a, scale2);
            qp[2 * c + 1] = mul2(bq, scale2);
        }
    }
    __syncthreads();

    // ---- k rows ----
    att_load_rows(buf, k, base, krow0, nk, t);
    __syncthreads();

    // ---- scores over the band (65 keys), 4 independent fma2 chains ----
    const uint64_t zero2 = pack2f(0.f, 0.f);
    float m = -1e30f;
#pragma unroll 2
    for (int ju = 0; ju <= 64; ju++) {
        int r = roff + ju;
        float s = -1e30f;
        if (full || r >= 0) {
            uint64_t A = zero2, B = zero2, Cc = zero2, Dd = zero2;
#pragma unroll
            for (int c = 0; c < 16; c += 2) {
                uint64_t k0, k1, k2, k3;
                lds_v2u64(k0, k1, sb + 4 * att_addr(r, c));
                lds_v2u64(k2, k3, sb + 4 * att_addr(r, c + 1));
                fma2(A, qp[2 * c], k0);
                fma2(B, qp[2 * c + 1], k1);
                fma2(Cc, qp[2 * c + 2], k2);
                fma2(Dd, qp[2 * c + 3], k3);
            }
            uint64_t t0 = add2(add2(A, B), add2(Cc, Dd));
            float e, o;
            unpack2f(t0, e, o);
            s = e + o;
            m = fmaxf(m, s);
        }
        sc[t * ATT_SC + ju] = s;
    }

    // ---- softmax over thread-private sc row ----
    float la = 0.f, lb = 0.f;
#pragma unroll 2
    for (int ju = 0; ju < 64; ju += 2) {
        float p0 = __expf(sc[t * ATT_SC + ju] - m);
        float p1 = __expf(sc[t * ATT_SC + ju + 1] - m);
        la += p0; lb += p1;
        sc[t * ATT_SC + ju] = p0;
        sc[t * ATT_SC + ju + 1] = p1;
    }
    {
        float p = __expf(sc[t * ATT_SC + 64] - m);
        la += p;
        sc[t * ATT_SC + 64] = p;
    }
    const float l = la + lb;
    __syncthreads();

    // ---- v rows (reuse buf) ----
    att_load_rows(buf, v, base, krow0, nk, t);
    __syncthreads();

    // ---- P @ V, packed accumulators over dim pairs ----
    uint64_t ap[32];
#pragma unroll
    for (int i = 0; i < 32; i++) ap[i] = zero2;
#pragma unroll 2
    for (int ju = 0; ju <= 64; ju++) {
        int r = roff + ju;
        if (full || r >= 0) {
            float p = sc[t * ATT_SC + ju];
            uint64_t pp = pack2f(p, p);
#pragma unroll
            for (int c = 0; c < 16; c += 2) {
                uint64_t v0, v1, v2, v3;
                lds_v2u64(v0, v1, sb + 4 * att_addr(r, c));
                lds_v2u64(v2, v3, sb + 4 * att_addr(r, c + 1));
                fma2(ap[2 * c], pp, v0);
                fma2(ap[2 * c + 1], pp, v1);
                fma2(ap[2 * c + 2], pp, v2);
                fma2(ap[2 * c + 3], pp, v3);
            }
        }
    }
    const float rinv = 1.f / l;

    // ---- fused bf16 hi/lo split, direct 16B stores ----
    const size_t obase = base + (size_t)qi * D_MODEL;
#pragma unroll
    for (int g = 0; g < 8; g++) {          // 8 dims per group = 4 packed pairs
        __nv_bfloat16 hv[8], lv[8];
#pragma unroll
        for (int e = 0; e < 4; e++) {
            float x0, x1;
            unpack2f(ap[g * 4 + e], x0, x1);
            float o0 = x0 * rinv, o1 = x1 * rinv;
            hv[2 * e] = __float2bfloat16(o0);
            lv[2 * e] = __float2bfloat16(o0 - __bfloat162float(hv[2 * e]));
            hv[2 * e + 1] = __float2bfloat16(o1);
            lv[2 * e + 1] = __float2bfloat16(o1 - __bfloat162float(hv[2 * e + 1]));
        }
        *(uint4*)(ohi + obase + g * 8) = *(uint4*)hv;
        *(uint4*)(olo + obase + g * 8) = *(uint4*)lv;
    }
}

// ---------------------------------------------------------------------------
extern "C" void kernel_launch(void* const* d_in, const int* in_sizes, int n_in,
                              void* d_out, int out_size)
{
    const float* x  = (const float*)d_in[0];
    const float* Wq = (const float*)d_in[1];
    const float* Wk = (const float*)d_in[2];
    const float* Wv = (const float*)d_in[3];
    const float* Wo = (const float*)d_in[4];
    float* out = (float*)d_out;

    float *q, *k, *v;
    __nv_bfloat16 *x_hi, *x_lo, *att_hi, *att_lo, *wt_hi, *wt_lo;
    cudaGetSymbolAddress((void**)&q, g_q);
    cudaGetSymbolAddress((void**)&k, g_k);
    cudaGetSymbolAddress((void**)&v, g_v);
    cudaGetSymbolAddress((void**)&x_hi, g_x_hi);
    cudaGetSymbolAddress((void**)&x_lo, g_x_lo);
    cudaGetSymbolAddress((void**)&att_hi, g_att_hi);
    cudaGetSymbolAddress((void**)&att_lo, g_att_lo);
    cudaGetSymbolAddress((void**)&wt_hi, g_wt_hi);
    cudaGetSymbolAddress((void**)&wt_lo, g_wt_lo);

    cudaFuncSetAttribute(gemm_mma_kernel,
                         cudaFuncAttributeMaxDynamicSharedMemorySize, GEMM_SMEM);
    cudaFuncSetAttribute(attn_kernel,
                         cudaFuncAttributeMaxDynamicSharedMemorySize, ATT_SMEM_BYTES);

    const size_t DD = (size_t)D_MODEL * D_MODEL;
    const int n4 = ROWS * D_MODEL / 4;

    // conversions: input split + fused 4-weight transpose/split
    split_kernel<<<(n4 + 255) / 256, 256>>>(x, x_hi, x_lo, n4);
    dim3 wgrid(32, 32, 4), wblk(32, 8);
    wsplit4_kernel<<<wgrid, wblk>>>(Wq, Wk, Wv, Wo, wt_hi, wt_lo);

    // fused QKV projection: B rows 0..3071 of wt (q,k,v contiguous)
    dim3 gqkv(3 * D_MODEL / 128, ROWS / 128);   // (24, 256)
    gemm_mma_kernel<<<gqkv, 256, GEMM_SMEM>>>(x_hi, x_lo, wt_hi, wt_lo, q, k, v);

    // attention: half-chunk CTAs, 2 CTAs/SM
    dim3 attn_grid(NH, 2 * NCHUNK, BATCH);      // (16, 64, 4)
    attn_kernel<<<attn_grid, 128, ATT_SMEM_BYTES>>>(q, k, v, att_hi, att_lo);

    // output projection (single weight -> grid.x = 8, w always 0)
    dim3 go(D_MODEL / 128, ROWS / 128);
    gemm_mma_kernel<<<go, 256, GEMM_SMEM>>>(att_hi, att_lo,
                                            wt_hi + 3 * DD, wt_lo + 3 * DD,
                                            out, out, out);
}

// round 10
// speedup vs baseline: 1.1614x; 1.1614x over previous
#include <cuda_runtime.h>
#include <cuda_bf16.h>
#include <cuda_fp16.h>
#include <cstdint>

#define D_MODEL 1024
#define NH 16
#define HD 64
#define CHUNK 256
#define WIN 64
#define BATCH 4
#define SEQ 8192
#define NCHUNK (SEQ / CHUNK)
#define ROWS (BATCH * SEQ)

// ---------------- scratch (__device__ globals; no allocs allowed) ----------
__device__ float g_q[ROWS * D_MODEL];
__device__ float g_k[ROWS * D_MODEL];
__device__ float g_v[ROWS * D_MODEL];
__device__ __nv_bfloat16 g_x_hi[ROWS * D_MODEL];
__device__ __nv_bfloat16 g_x_lo[ROWS * D_MODEL];
__device__ __nv_bfloat16 g_att_hi[ROWS * D_MODEL];
__device__ __nv_bfloat16 g_att_lo[ROWS * D_MODEL];
// 4 transposed weights (q,k,v,o), hi/lo limbs, each [N=1024][K=1024] (K-major)
__device__ __nv_bfloat16 g_wt_hi[4 * D_MODEL * D_MODEL];
__device__ __nv_bfloat16 g_wt_lo[4 * D_MODEL * D_MODEL];

// ---------------------------------------------------------------------------
// helpers
// ---------------------------------------------------------------------------
__device__ __forceinline__ uint32_t smem_u32(const void* p) {
    uint32_t a;
    asm("{ .reg .u64 t; cvta.to.shared.u64 t, %1; cvt.u32.u64 %0, t; }"
        : "=r"(a) : "l"(p));
    return a;
}

__device__ __forceinline__ void cp_async16(uint32_t dst, const void* src) {
    asm volatile("cp.async.cg.shared.global [%0], [%1], 16;"
                 :: "r"(dst), "l"(src) : "memory");
}
__device__ __forceinline__ void cp_commit() {
    asm volatile("cp.async.commit_group;" ::: "memory");
}
__device__ __forceinline__ void cp_wait1() {
    asm volatile("cp.async.wait_group 1;" ::: "memory");
}

__device__ __forceinline__ void ldsm_x4(uint32_t* r, uint32_t addr) {
    asm volatile("ldmatrix.sync.aligned.m8n8.x4.shared.b16 {%0,%1,%2,%3}, [%4];"
                 : "=r"(r[0]), "=r"(r[1]), "=r"(r[2]), "=r"(r[3]) : "r"(addr));
}

__device__ __forceinline__ void mma16816(float* c, const uint32_t* a, const uint32_t* b) {
    asm volatile(
        "mma.sync.aligned.m16n8k16.row.col.f32.bf16.bf16.f32 "
        "{%0,%1,%2,%3}, {%4,%5,%6,%7}, {%8,%9}, {%0,%1,%2,%3};"
        : "+f"(c[0]), "+f"(c[1]), "+f"(c[2]), "+f"(c[3])
        : "r"(a[0]), "r"(a[1]), "r"(a[2]), "r"(a[3]), "r"(b[0]), "r"(b[1]));
}

// ---- packed f32x2 ops (FFMA2 path, PTX-only per SASS_QUICKREF) ----
__device__ __forceinline__ uint64_t pack2f(float lo, float hi) {
    uint64_t r;
    asm("mov.b64 %0, {%1,%2};" : "=l"(r) : "f"(lo), "f"(hi));
    return r;
}
__device__ __forceinline__ void unpack2f(uint64_t p, float& lo, float& hi) {
    asm("mov.b64 {%0,%1}, %2;" : "=f"(lo), "=f"(hi) : "l"(p));
}
__device__ __forceinline__ void fma2(uint64_t& d, uint64_t a, uint64_t b) {
    asm("fma.rn.f32x2 %0, %1, %2, %0;" : "+l"(d) : "l"(a), "l"(b));
}
__device__ __forceinline__ uint64_t mul2(uint64_t a, uint64_t b) {
    uint64_t r;
    asm("mul.rn.f32x2 %0, %1, %2;" : "=l"(r) : "l"(a), "l"(b));
    return r;
}
__device__ __forceinline__ uint64_t add2(uint64_t a, uint64_t b) {
    uint64_t r;
    asm("add.rn.f32x2 %0, %1, %2;" : "=l"(r) : "l"(a), "l"(b));
    return r;
}
__device__ __forceinline__ void lds_v2u64(uint64_t& a, uint64_t& b, uint32_t addr) {
    asm volatile("ld.shared.v2.b64 {%0,%1}, [%2];" : "=l"(a), "=l"(b) : "r"(addr));
}

// tile geometry: 128 rows x 32 bf16 cols = 64B rows, 4x 16B chunks per row
// swizzled 16B-chunk: c' = c ^ ((r>>1)&3)
#define TILE_B 8192
#define STAGE_B (4 * TILE_B)   // Ahi, Alo, Bhi, Blo
#define NSTAGE 3
#define GEMM_SMEM (NSTAGE * STAGE_B)  // 98304
#define KIT 32                 // 1024 / 32

__device__ __forceinline__ uint32_t sw_addr(uint32_t tile_base, int r, int c) {
    return tile_base + r * 64 + ((c ^ ((r >> 1) & 3)) << 4);
}

// ---------------------------------------------------------------------------
// Split fp32 -> bf16 hi/lo limbs
// ---------------------------------------------------------------------------
__global__ __launch_bounds__(256) void split_kernel(
    const float* __restrict__ in, __nv_bfloat16* __restrict__ hi,
    __nv_bfloat16* __restrict__ lo, int n4)
{
    int i = blockIdx.x * blockDim.x + threadIdx.x;
    if (i >= n4) return;
    float4 x = ((const float4*)in)[i];
    float v[4] = {x.x, x.y, x.z, x.w};
    __nv_bfloat16 h[4], l[4];
#pragma unroll
    for (int j = 0; j < 4; j++) {
        h[j] = __float2bfloat16(v[j]);
        l[j] = __float2bfloat16(v[j] - __bfloat162float(h[j]));
    }
    *(uint2*)(hi + 4 * (size_t)i) = *(uint2*)h;
    *(uint2*)(lo + 4 * (size_t)i) = *(uint2*)l;
}

// Fused weight transpose + split for all 4 weights (grid.z selects W)
__global__ __launch_bounds__(256) void wsplit4_kernel(
    const float* __restrict__ W0, const float* __restrict__ W1,
    const float* __restrict__ W2, const float* __restrict__ W3,
    __nv_bfloat16* __restrict__ hiT, __nv_bfloat16* __restrict__ loT)
{
    __shared__ float tile[32][33];
    const int z = blockIdx.z;
    const float* W = (z == 0) ? W0 : (z == 1) ? W1 : (z == 2) ? W2 : W3;
    const size_t off = (size_t)z * D_MODEL * D_MODEL;
    int bx = blockIdx.x * 32, by = blockIdx.y * 32;
    int tx = threadIdx.x, ty = threadIdx.y;  // 32x8
#pragma unroll
    for (int r = ty; r < 32; r += 8)
        tile[r][tx] = W[(size_t)(by + r) * D_MODEL + bx + tx];
    __syncthreads();
#pragma unroll
    for (int r = ty; r < 32; r += 8) {
        float v = tile[tx][r];  // = W[(by+tx)*D + bx+r]
        __nv_bfloat16 h = __float2bfloat16(v);
        size_t o = off + (size_t)(bx + r) * D_MODEL + by + tx;
        hiT[o] = h;
        loT[o] = __float2bfloat16(v - __bfloat162float(h));
    }
}

// ---------------------------------------------------------------------------
// bf16-split GEMM via mma.sync, multi-output variant.
// B spans blockIdx.x*128 rows of the (possibly concatenated) weight matrix;
// output tensor = C[blockIdx.x >> 3], column = blockIdx.x & 7.
// CTA 128x128, BK=32, 3-stage cp.async pipeline, 8 warps, 2 CTAs/SM.
// ---------------------------------------------------------------------------
__global__ __launch_bounds__(256, 2) void gemm_mma_kernel(
    const __nv_bfloat16* __restrict__ Ahi, const __nv_bfloat16* __restrict__ Alo,
    const __nv_bfloat16* __restrict__ Bhi, const __nv_bfloat16* __restrict__ Blo,
    float* __restrict__ C0, float* __restrict__ C1, float* __restrict__ C2)
{
    extern __shared__ char smem[];
    const uint32_t sbase = smem_u32(smem);
    const int tid = threadIdx.x;
    const int lane = tid & 31;
    const int wid = tid >> 5;
    const int wm = wid >> 2;        // 0..1
    const int wn = wid & 3;         // 0..3
    const int m0 = blockIdx.y * 128;
    const int nB = blockIdx.x * 128;        // row in the B (weight) matrix
    const int w = nB >> 10;
    const int col0 = nB & 1023;
    float* __restrict__ C = (w == 0) ? C0 : (w == 1) ? C1 : C2;

    const __nv_bfloat16* srcs[4] = {Ahi, Alo, Bhi, Blo};

    auto load_stage = [&](int stage, int k0) {
        uint32_t sb = sbase + stage * STAGE_B;
#pragma unroll
        for (int t = 0; t < 4; t++) {
            int row0 = (t < 2) ? m0 : nB;
            const __nv_bfloat16* s = srcs[t];
#pragma unroll
            for (int i = 0; i < 2; i++) {
                int cid = tid + i * 256;       // 0..511
                int r = cid >> 2;
                int c = cid & 3;
                const void* g = s + (size_t)(row0 + r) * D_MODEL + k0 + c * 8;
                cp_async16(sw_addr(sb + t * TILE_B, r, c), g);
            }
        }
    };

    float acc[4][4][4];
#pragma unroll
    for (int i = 0; i < 4; i++)
#pragma unroll
        for (int j = 0; j < 4; j++)
#pragma unroll
            for (int e = 0; e < 4; e++) acc[i][j][e] = 0.f;

    load_stage(0, 0);
    cp_commit();
    load_stage(1, 32);
    cp_commit();

    const int a_r = lane & 15;
    const int a_c = lane >> 4;
    const int b_r = (lane & 7) + ((lane >> 4) << 3);
    const int b_c = (lane >> 3) & 1;

    for (int it = 0; it < KIT; it++) {
        cp_wait1();
        __syncthreads();
        if (it + 2 < KIT) load_stage((it + 2) % NSTAGE, (it + 2) * 32);
        cp_commit();

        const uint32_t sb = sbase + (it % NSTAGE) * STAGE_B;
        const uint32_t tAhi = sb;
        const uint32_t tAlo = sb + TILE_B;
        const uint32_t tBhi = sb + 2 * TILE_B;
        const uint32_t tBlo = sb + 3 * TILE_B;

#pragma unroll
        for (int ks = 0; ks < 2; ks++) {
            uint32_t a[4][4], bh[4][2], bl[4][2];
#pragma unroll
            for (int mt = 0; mt < 4; mt++) {
                int r = wm * 64 + mt * 16 + a_r;
                ldsm_x4(a[mt], sw_addr(tAhi, r, ks * 2 + a_c));
            }
#pragma unroll
            for (int np = 0; np < 2; np++) {
                uint32_t t4[4];
                int r = wn * 32 + np * 16 + b_r;
                ldsm_x4(t4, sw_addr(tBhi, r, ks * 2 + b_c));
                bh[np * 2][0] = t4[0]; bh[np * 2][1] = t4[1];
                bh[np * 2 + 1][0] = t4[2]; bh[np * 2 + 1][1] = t4[3];
            }
#pragma unroll
            for (int np = 0; np < 2; np++) {
                uint32_t t4[4];
                int r = wn * 32 + np * 16 + b_r;
                ldsm_x4(t4, sw_addr(tBlo, r, ks * 2 + b_c));
                bl[np * 2][0] = t4[0]; bl[np * 2][1] = t4[1];
                bl[np * 2 + 1][0] = t4[2]; bl[np * 2 + 1][1] = t4[3];
            }
#pragma unroll
            for (int mt = 0; mt < 4; mt++)
#pragma unroll
                for (int nt = 0; nt < 4; nt++)
                    mma16816(acc[mt][nt], a[mt], bh[nt]);
#pragma unroll
            for (int mt = 0; mt < 4; mt++)
#pragma unroll
                for (int nt = 0; nt < 4; nt++)
                    mma16816(acc[mt][nt], a[mt], bl[nt]);
#pragma unroll
            for (int mt = 0; mt < 4; mt++) {
                int r = wm * 64 + mt * 16 + a_r;
                ldsm_x4(a[mt], sw_addr(tAlo, r, ks * 2 + a_c));
            }
#pragma unroll
            for (int mt = 0; mt < 4; mt++)
#pragma unroll
                for (int nt = 0; nt < 4; nt++)
                    mma16816(acc[mt][nt], a[mt], bh[nt]);
        }
    }

    const int er = lane >> 2;
    const int ec = (lane & 3) * 2;
#pragma unroll
    for (int mt = 0; mt < 4; mt++) {
#pragma unroll
        for (int nt = 0; nt < 4; nt++) {
            int row = m0 + wm * 64 + mt * 16 + er;
            int col = col0 + wn * 32 + nt * 8 + ec;
            *(float2*)(C + (size_t)row * D_MODEL + col) =
                make_float2(acc[mt][nt][0], acc[mt][nt][1]);
            *(float2*)(C + (size_t)(row + 8) * D_MODEL + col) =
                make_float2(acc[mt][nt][2], acc[mt][nt][3]);
        }
    }
}

// ---------------------------------------------------------------------------
// Banded chunk-local attention: full 256-query CTA, 128 threads,
// 2 adjacent queries/thread (k/v row loads shared -> half LDS traffic).
// Fused score+exp pass (no max subtraction: |s| <= |q||k|/8 <= 8, exp safe
// in fp32); probs stored fp16 -> smem 99.8 KB -> 2 CTAs/SM.
// k/v smem: stride 64 floats, 16B chunks swizzled by ((r>>1)&7)
// (paired rows 2t,2t+1 share swizzle; 8 lane-phases hit distinct chunks).
// ---------------------------------------------------------------------------
#define ATT_SC 67   // fp16 elements per prob row
#define ATT_SMEM_BYTES (CHUNK * 64 * 4 + CHUNK * ATT_SC * 2)  // 99840

__device__ __forceinline__ int att_addr(int r, int c) {  // float index, c = 16B chunk
    return r * 64 + ((c ^ ((r >> 1) & 7)) << 2);
}

__device__ __forceinline__ void att_load_tile(
    float* __restrict__ buf, const float* __restrict__ src, size_t base, int tid)
{
#pragma unroll
    for (int i = 0; i < 32; i++) {
        int idx = tid + i * 128;          // 0..4095
        int r = idx >> 4;
        int c = idx & 15;
        float4 t = *(const float4*)(src + base + (size_t)r * D_MODEL + c * 4);
        *(float4*)(buf + att_addr(r, c)) = t;
    }
}

__global__ __launch_bounds__(128) void attn_kernel(
    const float* __restrict__ q, const float* __restrict__ k,
    const float* __restrict__ v,
    __nv_bfloat16* __restrict__ ohi, __nv_bfloat16* __restrict__ olo)
{
    extern __shared__ float fsmem[];
    float* buf = fsmem;                          // [256][64] swizzled
    __half* sc = (__half*)(fsmem + CHUNK * 64);  // [256][67] probs
    const uint32_t sb = smem_u32(fsmem);

    const int h = blockIdx.x;
    const int n = blockIdx.y;
    const int b = blockIdx.z;
    const int t = threadIdx.x;               // 0..127
    const int q0 = 2 * t;
    const int q1 = 2 * t + 1;

    const size_t base = ((size_t)(b * SEQ + n * CHUNK)) * D_MODEL + h * HD;

    // ---- stage q, pull both rows into packed registers (pre-scaled) ----
    att_load_tile(buf, q, base, t);
    __syncthreads();
    uint64_t qp0[32], qp1[32];
    {
        const uint64_t scale2 = pack2f(0.125f, 0.125f);
#pragma unroll
        for (int c = 0; c < 16; c++) {
            uint64_t a, bq;
            lds_v2u64(a, bq, sb + 4 * att_addr(q0, c));
            qp0[2 * c] = mul2(a, scale2); qp0[2 * c + 1] = mul2(bq, scale2);
            lds_v2u64(a, bq, sb + 4 * att_addr(q1, c));
            qp1[2 * c] = mul2(a, scale2); qp1[2 * c + 1] = mul2(bq, scale2);
        }
    }
    __syncthreads();

    // ---- k tile ----
    att_load_tile(buf, k, base, t);
    __syncthreads();

    // ---- fused score + exp pass (one k-row load serves both queries) ----
    const uint64_t zero2 = pack2f(0.f, 0.f);
    float l0 = 0.f, l1 = 0.f;
#pragma unroll 2
    for (int ju = 0; ju <= 65; ju++) {
        int j = q0 - 64 + ju;                 // key row
        float p0f = 0.f, p1f = 0.f;
        if (j >= 0) {
            uint64_t a0a = zero2, a0b = zero2, a1a = zero2, a1b = zero2;
#pragma unroll
            for (int c = 0; c < 16; c += 2) {   // 2 chunks = 8 floats per step
                uint64_t k0, k1, k2, k3;
                lds_v2u64(k0, k1, sb + 4 * att_addr(j, c));
                lds_v2u64(k2, k3, sb + 4 * att_addr(j, c + 1));
                fma2(a0a, qp0[2 * c], k0);     fma2(a1a, qp1[2 * c], k0);
                fma2(a0b, qp0[2 * c + 1], k1); fma2(a1b, qp1[2 * c + 1], k1);
                fma2(a0a, qp0[2 * c + 2], k2); fma2(a1a, qp1[2 * c + 2], k2);
                fma2(a0b, qp0[2 * c + 3], k3); fma2(a1b, qp1[2 * c + 3], k3);
            }
            uint64_t t0 = add2(a0a, a0b);
            uint64_t t1 = add2(a1a, a1b);
            float e0, o0, e1, o1;
            unpack2f(t0, e0, o0);
            unpack2f(t1, e1, o1);
            if (ju <= 64) p0f = __expf(e0 + o0);
            if (ju >= 1)  p1f = __expf(e1 + o1);
        }
        __half h0 = __float2half(p0f);
        __half h1 = __float2half(p1f);
        l0 += __half2float(h0);               // denominator matches stored weights
        l1 += __half2float(h1);
        sc[q0 * ATT_SC + ju] = h0;
        sc[q1 * ATT_SC + ju] = h1;
    }
    __syncthreads();

    // ---- v tile (reuse buf) ----
    att_load_tile(buf, v, base, t);
    __syncthreads();

    // ---- P @ V; packed accumulators over dim pairs ----
    uint64_t ap0[32], ap1[32];
#pragma unroll
    for (int i = 0; i < 32; i++) { ap0[i] = zero2; ap1[i] = zero2; }
#pragma unroll 2
    for (int ju = 0; ju <= 65; ju++) {
        int j = q0 - 64 + ju;
        if (j >= 0) {
            float p0 = __half2float(sc[q0 * ATT_SC + ju]);
            float p1 = __half2float(sc[q1 * ATT_SC + ju]);
            uint64_t pp0 = pack2f(p0, p0);
            uint64_t pp1 = pack2f(p1, p1);
#pragma unroll
            for (int c = 0; c < 16; c += 2) {
                uint64_t v0, v1, v2, v3;
                lds_v2u64(v0, v1, sb + 4 * att_addr(j, c));
                lds_v2u64(v2, v3, sb + 4 * att_addr(j, c + 1));
                fma2(ap0[2 * c], pp0, v0);     fma2(ap1[2 * c], pp1, v0);
                fma2(ap0[2 * c + 1], pp0, v1); fma2(ap1[2 * c + 1], pp1, v1);
                fma2(ap0[2 * c + 2], pp0, v2); fma2(ap1[2 * c + 2], pp1, v2);
                fma2(ap0[2 * c + 3], pp0, v3); fma2(ap1[2 * c + 3], pp1, v3);
            }
        }
    }
    const float r0 = 1.f / l0;
    const float r1 = 1.f / l1;

    // ---- fused bf16 hi/lo split, direct 16B stores (2 rows) ----
#pragma unroll
    for (int g = 0; g < 8; g++) {          // 8 dims per group = 4 packed pairs
        __nv_bfloat16 hv0[8], lv0[8], hv1[8], lv1[8];
#pragma unroll
        for (int e = 0; e < 4; e++) {
            float x0, x1, y0, y1;
            unpack2f(ap0[g * 4 + e], x0, x1);
            unpack2f(ap1[g * 4 + e], y0, y1);
            float o00 = x0 * r0, o01 = x1 * r0;
            float o10 = y0 * r1, o11 = y1 * r1;
            hv0[2 * e] = __float2bfloat16(o00);
            lv0[2 * e] = __float2bfloat16(o00 - __bfloat162float(hv0[2 * e]));
            hv0[2 * e + 1] = __float2bfloat16(o01);
            lv0[2 * e + 1] = __float2bfloat16(o01 - __bfloat162float(hv0[2 * e + 1]));
            hv1[2 * e] = __float2bfloat16(o10);
            lv1[2 * e] = __float2bfloat16(o10 - __bfloat162float(hv1[2 * e]));
            hv1[2 * e + 1] = __float2bfloat16(o11);
            lv1[2 * e + 1] = __float2bfloat16(o11 - __bfloat162float(hv1[2 * e + 1]));
        }
        *(uint4*)(ohi + base + (size_t)q0 * D_MODEL + g * 8) = *(uint4*)hv0;
        *(uint4*)(olo + base + (size_t)q0 * D_MODEL + g * 8) = *(uint4*)lv0;
        *(uint4*)(ohi + base + (size_t)q1 * D_MODEL + g * 8) = *(uint4*)hv1;
        *(uint4*)(olo + base + (size_t)q1 * D_MODEL + g * 8) = *(uint4*)lv1;
    }
}

// ---------------------------------------------------------------------------
extern "C" void kernel_launch(void* const* d_in, const int* in_sizes, int n_in,
                              void* d_out, int out_size)
{
    const float* x  = (const float*)d_in[0];
    const float* Wq = (const float*)d_in[1];
    const float* Wk = (const float*)d_in[2];
    const float* Wv = (const float*)d_in[3];
    const float* Wo = (const float*)d_in[4];
    float* out = (float*)d_out;

    float *q, *k, *v;
    __nv_bfloat16 *x_hi, *x_lo, *att_hi, *att_lo, *wt_hi, *wt_lo;
    cudaGetSymbolAddress((void**)&q, g_q);
    cudaGetSymbolAddress((void**)&k, g_k);
    cudaGetSymbolAddress((void**)&v, g_v);
    cudaGetSymbolAddress((void**)&x_hi, g_x_hi);
    cudaGetSymbolAddress((void**)&x_lo, g_x_lo);
    cudaGetSymbolAddress((void**)&att_hi, g_att_hi);
    cudaGetSymbolAddress((void**)&att_lo, g_att_lo);
    cudaGetSymbolAddress((void**)&wt_hi, g_wt_hi);
    cudaGetSymbolAddress((void**)&wt_lo, g_wt_lo);

    cudaFuncSetAttribute(gemm_mma_kernel,
                         cudaFuncAttributeMaxDynamicSharedMemorySize, GEMM_SMEM);
    cudaFuncSetAttribute(attn_kernel,
                         cudaFuncAttributeMaxDynamicSharedMemorySize, ATT_SMEM_BYTES);

    const size_t DD = (size_t)D_MODEL * D_MODEL;
    const int n4 = ROWS * D_MODEL / 4;

    // conversions: input split + fused 4-weight transpose/split
    split_kernel<<<(n4 + 255) / 256, 256>>>(x, x_hi, x_lo, n4);
    dim3 wgrid(32, 32, 4), wblk(32, 8);
    wsplit4_kernel<<<wgrid, wblk>>>(Wq, Wk, Wv, Wo, wt_hi, wt_lo);

    // fused QKV projection: B rows 0..3071 of wt (q,k,v contiguous)
    dim3 gqkv(3 * D_MODEL / 128, ROWS / 128);   // (24, 256)
    gemm_mma_kernel<<<gqkv, 256, GEMM_SMEM>>>(x_hi, x_lo, wt_hi, wt_lo, q, k, v);

    // attention: 256-query CTAs, 2 queries/thread, fp16 probs -> 2 CTAs/SM
    dim3 attn_grid(NH, NCHUNK, BATCH);          // (16, 32, 4)
    attn_kernel<<<attn_grid, 128, ATT_SMEM_BYTES>>>(q, k, v, att_hi, att_lo);

    // output projection (single weight -> grid.x = 8, w always 0)
    dim3 go(D_MODEL / 128, ROWS / 128);
    gemm_mma_kernel<<<go, 256, GEMM_SMEM>>>(att_hi, att_lo,
                                            wt_hi + 3 * DD, wt_lo + 3 * DD,
                                            out, out, out);
}

// round 11
// speedup vs baseline: 1.5156x; 1.3050x over previous
#include <cuda_runtime.h>
#include <cuda_bf16.h>
#include <cuda_fp16.h>
#include <cstdint>

#define D_MODEL 1024
#define NH 16
#define HD 64
#define CHUNK 256
#define WIN 64
#define BATCH 4
#define SEQ 8192
#define NCHUNK (SEQ / CHUNK)
#define ROWS (BATCH * SEQ)

// Weights pre-scaled by 32 (keeps fp16 lo-limb out of denormals); GEMM
// epilogue multiplies by 1/32.
#define WSCALE 32.0f
#define OSCALE (1.0f / 32.0f)

// ---------------- scratch (__device__ globals; no allocs allowed) ----------
__device__ float g_q[ROWS * D_MODEL];
__device__ float g_k[ROWS * D_MODEL];
__device__ float g_v[ROWS * D_MODEL];
__device__ __half g_x_h[ROWS * D_MODEL];     // fp16(x), single limb
__device__ __half g_att_h[ROWS * D_MODEL];   // fp16(att), single limb
// 4 transposed weights (q,k,v,o), fp16 hi/lo limbs of 32*W, [N=1024][K=1024]
__device__ __half g_wt_h[4 * D_MODEL * D_MODEL];
__device__ __half g_wt_l[4 * D_MODEL * D_MODEL];

// ---------------------------------------------------------------------------
// helpers
// ---------------------------------------------------------------------------
__device__ __forceinline__ uint32_t smem_u32(const void* p) {
    uint32_t a;
    asm("{ .reg .u64 t; cvta.to.shared.u64 t, %1; cvt.u32.u64 %0, t; }"
        : "=r"(a) : "l"(p));
    return a;
}

__device__ __forceinline__ void cp_async16(uint32_t dst, const void* src) {
    asm volatile("cp.async.cg.shared.global [%0], [%1], 16;"
                 :: "r"(dst), "l"(src) : "memory");
}
__device__ __forceinline__ void cp_commit() {
    asm volatile("cp.async.commit_group;" ::: "memory");
}
__device__ __forceinline__ void cp_wait1() {
    asm volatile("cp.async.wait_group 1;" ::: "memory");
}

__device__ __forceinline__ void ldsm_x4(uint32_t* r, uint32_t addr) {
    asm volatile("ldmatrix.sync.aligned.m8n8.x4.shared.b16 {%0,%1,%2,%3}, [%4];"
                 : "=r"(r[0]), "=r"(r[1]), "=r"(r[2]), "=r"(r[3]) : "r"(addr));
}

// fp16 mma, fp32 accumulate
__device__ __forceinline__ void mma16816h(float* c, const uint32_t* a, const uint32_t* b) {
    asm volatile(
        "mma.sync.aligned.m16n8k16.row.col.f32.f16.f16.f32 "
        "{%0,%1,%2,%3}, {%4,%5,%6,%7}, {%8,%9}, {%0,%1,%2,%3};"
        : "+f"(c[0]), "+f"(c[1]), "+f"(c[2]), "+f"(c[3])
        : "r"(a[0]), "r"(a[1]), "r"(a[2]), "r"(a[3]), "r"(b[0]), "r"(b[1]));
}

// ---- packed f32x2 ops (FFMA2 path, PTX-only per SASS_QUICKREF) ----
__device__ __forceinline__ uint64_t pack2f(float lo, float hi) {
    uint64_t r;
    asm("mov.b64 %0, {%1,%2};" : "=l"(r) : "f"(lo), "f"(hi));
    return r;
}
__device__ __forceinline__ void unpack2f(uint64_t p, float& lo, float& hi) {
    asm("mov.b64 {%0,%1}, %2;" : "=f"(lo), "=f"(hi) : "l"(p));
}
__device__ __forceinline__ void fma2(uint64_t& d, uint64_t a, uint64_t b) {
    asm("fma.rn.f32x2 %0, %1, %2, %0;" : "+l"(d) : "l"(a), "l"(b));
}
__device__ __forceinline__ uint64_t mul2(uint64_t a, uint64_t b) {
    uint64_t r;
    asm("mul.rn.f32x2 %0, %1, %2;" : "=l"(r) : "l"(a), "l"(b));
    return r;
}
__device__ __forceinline__ uint64_t add2(uint64_t a, uint64_t b) {
    uint64_t r;
    asm("add.rn.f32x2 %0, %1, %2;" : "=l"(r) : "l"(a), "l"(b));
    return r;
}
__device__ __forceinline__ void lds_v2u64(uint64_t& a, uint64_t& b, uint32_t addr) {
    asm volatile("ld.shared.v2.b64 {%0,%1}, [%2];" : "=l"(a), "=l"(b) : "r"(addr));
}

// tile geometry: 128 rows x 32 fp16 cols = 64B rows, 4x 16B chunks per row
#define TILE_B 8192
#define STAGE_B (3 * TILE_B)   // A, Bhi, Blo
#define NSTAGE 3
#define GEMM_SMEM (NSTAGE * STAGE_B)  // 73728
#define KIT 32                 // 1024 / 32

__device__ __forceinline__ uint32_t sw_addr(uint32_t tile_base, int r, int c) {
    return tile_base + r * 64 + ((c ^ ((r >> 1) & 3)) << 4);
}

// ---------------------------------------------------------------------------
// fp32 -> fp16 (single limb) for activations
// ---------------------------------------------------------------------------
__global__ __launch_bounds__(256) void split_h_kernel(
    const float* __restrict__ in, __half* __restrict__ out, int n4)
{
    int i = blockIdx.x * blockDim.x + threadIdx.x;
    if (i >= n4) return;
    float4 x = ((const float4*)in)[i];
    __half h[4] = {__float2half(x.x), __float2half(x.y),
                   __float2half(x.z), __float2half(x.w)};
    *(uint2*)(out + 4 * (size_t)i) = *(uint2*)h;
}

// Fused weight transpose + fp16 hi/lo split of 32*W (grid.z selects W)
__global__ __launch_bounds__(256) void wsplit4_kernel(
    const float* __restrict__ W0, const float* __restrict__ W1,
    const float* __restrict__ W2, const float* __restrict__ W3,
    __half* __restrict__ hiT, __half* __restrict__ loT)
{
    __shared__ float tile[32][33];
    const int z = blockIdx.z;
    const float* W = (z == 0) ? W0 : (z == 1) ? W1 : (z == 2) ? W2 : W3;
    const size_t off = (size_t)z * D_MODEL * D_MODEL;
    int bx = blockIdx.x * 32, by = blockIdx.y * 32;
    int tx = threadIdx.x, ty = threadIdx.y;  // 32x8
#pragma unroll
    for (int r = ty; r < 32; r += 8)
        tile[r][tx] = W[(size_t)(by + r) * D_MODEL + bx + tx];
    __syncthreads();
#pragma unroll
    for (int r = ty; r < 32; r += 8) {
        float v = tile[tx][r] * WSCALE;  // = 32 * W[(by+tx)*D + bx+r]
        __half h = __float2half(v);
        size_t o = off + (size_t)(bx + r) * D_MODEL + by + tx;
        hiT[o] = h;
        loT[o] = __float2half(v - __half2float(h));
    }
}

// ---------------------------------------------------------------------------
// 2-pass fp16 GEMM via mma.sync: C = (1/32) * A_fp16 @ (Bhi+Blo)^T, fp32 acc.
// A: single fp16 limb. B: 2-limb fp16 of 32*W (K-major, pre-transposed).
// CTA 128x128, BK=32, 3-stage cp.async pipeline (3 tiles/stage = 24KB),
// 8 warps (2m x 4n), 2 CTAs/SM. Multi-output: C[blockIdx.x>>3].
// ---------------------------------------------------------------------------
__global__ __launch_bounds__(256, 2) void gemm_mma_kernel(
    const __half* __restrict__ A,
    const __half* __restrict__ Bhi, const __half* __restrict__ Blo,
    float* __restrict__ C0, float* __restrict__ C1, float* __restrict__ C2)
{
    extern __shared__ char smem[];
    const uint32_t sbase = smem_u32(smem);
    const int tid = threadIdx.x;
    const int lane = tid & 31;
    const int wid = tid >> 5;
    const int wm = wid >> 2;        // 0..1
    const int wn = wid & 3;         // 0..3
    const int m0 = blockIdx.y * 128;
    const int nB = blockIdx.x * 128;        // row in the B (weight) matrix
    const int w = nB >> 10;
    const int col0 = nB & 1023;
    float* __restrict__ C = (w == 0) ? C0 : (w == 1) ? C1 : C2;

    const __half* srcs[3] = {A, Bhi, Blo};

    auto load_stage = [&](int stage, int k0) {
        uint32_t sb = sbase + stage * STAGE_B;
#pragma unroll
        for (int t = 0; t < 3; t++) {
            int row0 = (t == 0) ? m0 : nB;
            const __half* s = srcs[t];
#pragma unroll
            for (int i = 0; i < 2; i++) {
                int cid = tid + i * 256;       // 0..511
                int r = cid >> 2;
                int c = cid & 3;
                const void* g = s + (size_t)(row0 + r) * D_MODEL + k0 + c * 8;
                cp_async16(sw_addr(sb + t * TILE_B, r, c), g);
            }
        }
    };

    float acc[4][4][4];
#pragma unroll
    for (int i = 0; i < 4; i++)
#pragma unroll
        for (int j = 0; j < 4; j++)
#pragma unroll
            for (int e = 0; e < 4; e++) acc[i][j][e] = 0.f;

    load_stage(0, 0);
    cp_commit();
    load_stage(1, 32);
    cp_commit();

    const int a_r = lane & 15;
    const int a_c = lane >> 4;
    const int b_r = (lane & 7) + ((lane >> 4) << 3);
    const int b_c = (lane >> 3) & 1;

    for (int it = 0; it < KIT; it++) {
        cp_wait1();
        __syncthreads();
        if (it + 2 < KIT) load_stage((it + 2) % NSTAGE, (it + 2) * 32);
        cp_commit();

        const uint32_t sb = sbase + (it % NSTAGE) * STAGE_B;
        const uint32_t tA  = sb;
        const uint32_t tBh = sb + TILE_B;
        const uint32_t tBl = sb + 2 * TILE_B;

#pragma unroll
        for (int ks = 0; ks < 2; ks++) {
            uint32_t a[4][4], bh[4][2], bl[4][2];
#pragma unroll
            for (int mt = 0; mt < 4; mt++) {
                int r = wm * 64 + mt * 16 + a_r;
                ldsm_x4(a[mt], sw_addr(tA, r, ks * 2 + a_c));
            }
#pragma unroll
            for (int np = 0; np < 2; np++) {
                uint32_t t4[4];
                int r = wn * 32 + np * 16 + b_r;
                ldsm_x4(t4, sw_addr(tBh, r, ks * 2 + b_c));
                bh[np * 2][0] = t4[0]; bh[np * 2][1] = t4[1];
                bh[np * 2 + 1][0] = t4[2]; bh[np * 2 + 1][1] = t4[3];
            }
#pragma unroll
            for (int np = 0; np < 2; np++) {
                uint32_t t4[4];
                int r = wn * 32 + np * 16 + b_r;
                ldsm_x4(t4, sw_addr(tBl, r, ks * 2 + b_c));
                bl[np * 2][0] = t4[0]; bl[np * 2][1] = t4[1];
                bl[np * 2 + 1][0] = t4[2]; bl[np * 2 + 1][1] = t4[3];
            }
            // pass 1: A * Bhi
#pragma unroll
            for (int mt = 0; mt < 4; mt++)
#pragma unroll
                for (int nt = 0; nt < 4; nt++)
                    mma16816h(acc[mt][nt], a[mt], bh[nt]);
            // pass 2: A * Blo
#pragma unroll
            for (int mt = 0; mt < 4; mt++)
#pragma unroll
                for (int nt = 0; nt < 4; nt++)
                    mma16816h(acc[mt][nt], a[mt], bl[nt]);
        }
    }

    const int er = lane >> 2;
    const int ec = (lane & 3) * 2;
#pragma unroll
    for (int mt = 0; mt < 4; mt++) {
#pragma unroll
        for (int nt = 0; nt < 4; nt++) {
            int row = m0 + wm * 64 + mt * 16 + er;
            int col = col0 + wn * 32 + nt * 8 + ec;
            *(float2*)(C + (size_t)row * D_MODEL + col) =
                make_float2(acc[mt][nt][0] * OSCALE, acc[mt][nt][1] * OSCALE);
            *(float2*)(C + (size_t)(row + 8) * D_MODEL + col) =
                make_float2(acc[mt][nt][2] * OSCALE, acc[mt][nt][3] * OSCALE);
        }
    }
}

// ---------------------------------------------------------------------------
// Banded chunk-local attention: full 256-query CTA, 128 threads,
// 2 adjacent queries/thread (shared k/v row loads), fused score+exp
// (no max subtraction: |s| <= 8, exp safe in fp32), fp16 probs in smem
// (99.8 KB -> 2 CTAs/SM), fp16 single-limb output.
// ---------------------------------------------------------------------------
#define ATT_SC 67   // fp16 elements per prob row
#define ATT_SMEM_BYTES (CHUNK * 64 * 4 + CHUNK * ATT_SC * 2)  // 99840

__device__ __forceinline__ int att_addr(int r, int c) {  // float index, c = 16B chunk
    return r * 64 + ((c ^ ((r >> 1) & 7)) << 2);
}

__device__ __forceinline__ void att_load_tile(
    float* __restrict__ buf, const float* __restrict__ src, size_t base, int tid)
{
#pragma unroll
    for (int i = 0; i < 32; i++) {
        int idx = tid + i * 128;          // 0..4095
        int r = idx >> 4;
        int c = idx & 15;
        float4 t = *(const float4*)(src + base + (size_t)r * D_MODEL + c * 4);
        *(float4*)(buf + att_addr(r, c)) = t;
    }
}

__global__ __launch_bounds__(128) void attn_kernel(
    const float* __restrict__ q, const float* __restrict__ k,
    const float* __restrict__ v, __half* __restrict__ o)
{
    extern __shared__ float fsmem[];
    float* buf = fsmem;                          // [256][64] swizzled
    __half* sc = (__half*)(fsmem + CHUNK * 64);  // [256][67] probs
    const uint32_t sb = smem_u32(fsmem);

    const int h = blockIdx.x;
    const int n = blockIdx.y;
    const int b = blockIdx.z;
    const int t = threadIdx.x;               // 0..127
    const int q0 = 2 * t;
    const int q1 = 2 * t + 1;

    const size_t base = ((size_t)(b * SEQ + n * CHUNK)) * D_MODEL + h * HD;

    // ---- stage q, pull both rows into packed registers (pre-scaled) ----
    att_load_tile(buf, q, base, t);
    __syncthreads();
    uint64_t qp0[32], qp1[32];
    {
        const uint64_t scale2 = pack2f(0.125f, 0.125f);
#pragma unroll
        for (int c = 0; c < 16; c++) {
            uint64_t a, bq;
            lds_v2u64(a, bq, sb + 4 * att_addr(q0, c));
            qp0[2 * c] = mul2(a, scale2); qp0[2 * c + 1] = mul2(bq, scale2);
            lds_v2u64(a, bq, sb + 4 * att_addr(q1, c));
            qp1[2 * c] = mul2(a, scale2); qp1[2 * c + 1] = mul2(bq, scale2);
        }
    }
    __syncthreads();

    // ---- k tile ----
    att_load_tile(buf, k, base, t);
    __syncthreads();

    // ---- fused score + exp pass (one k-row load serves both queries) ----
    const uint64_t zero2 = pack2f(0.f, 0.f);
    float l0 = 0.f, l1 = 0.f;
#pragma unroll 2
    for (int ju = 0; ju <= 65; ju++) {
        int j = q0 - 64 + ju;                 // key row
        float p0f = 0.f, p1f = 0.f;
        if (j >= 0) {
            uint64_t a0a = zero2, a0b = zero2, a1a = zero2, a1b = zero2;
#pragma unroll
            for (int c = 0; c < 16; c += 2) {   // 2 chunks = 8 floats per step
                uint64_t k0, k1, k2, k3;
                lds_v2u64(k0, k1, sb + 4 * att_addr(j, c));
                lds_v2u64(k2, k3, sb + 4 * att_addr(j, c + 1));
                fma2(a0a, qp0[2 * c], k0);     fma2(a1a, qp1[2 * c], k0);
                fma2(a0b, qp0[2 * c + 1], k1); fma2(a1b, qp1[2 * c + 1], k1);
                fma2(a0a, qp0[2 * c + 2], k2); fma2(a1a, qp1[2 * c + 2], k2);
                fma2(a0b, qp0[2 * c + 3], k3); fma2(a1b, qp1[2 * c + 3], k3);
            }
            uint64_t t0 = add2(a0a, a0b);
            uint64_t t1 = add2(a1a, a1b);
            float e0, o0, e1, o1;
            unpack2f(t0, e0, o0);
            unpack2f(t1, e1, o1);
            if (ju <= 64) p0f = __expf(e0 + o0);
            if (ju >= 1)  p1f = __expf(e1 + o1);
        }
        __half h0 = __float2half(p0f);
        __half h1 = __float2half(p1f);
        l0 += __half2float(h0);               // denominator matches stored weights
        l1 += __half2float(h1);
        sc[q0 * ATT_SC + ju] = h0;
        sc[q1 * ATT_SC + ju] = h1;
    }
    __syncthreads();

    // ---- v tile (reuse buf) ----
    att_load_tile(buf, v, base, t);
    __syncthreads();

    // ---- P @ V; packed accumulators over dim pairs ----
    uint64_t ap0[32], ap1[32];
#pragma unroll
    for (int i = 0; i < 32; i++) { ap0[i] = zero2; ap1[i] = zero2; }
#pragma unroll 2
    for (int ju = 0; ju <= 65; ju++) {
        int j = q0 - 64 + ju;
        if (j >= 0) {
            float p0 = __half2float(sc[q0 * ATT_SC + ju]);
            float p1 = __half2float(sc[q1 * ATT_SC + ju]);
            uint64_t pp0 = pack2f(p0, p0);
            uint64_t pp1 = pack2f(p1, p1);
#pragma unroll
            for (int c = 0; c < 16; c += 2) {
                uint64_t v0, v1, v2, v3;
                lds_v2u64(v0, v1, sb + 4 * att_addr(j, c));
                lds_v2u64(v2, v3, sb + 4 * att_addr(j, c + 1));
                fma2(ap0[2 * c], pp0, v0);     fma2(ap1[2 * c], pp1, v0);
                fma2(ap0[2 * c + 1], pp0, v1); fma2(ap1[2 * c + 1], pp1, v1);
                fma2(ap0[2 * c + 2], pp0, v2); fma2(ap1[2 * c + 2], pp1, v2);
                fma2(ap0[2 * c + 3], pp0, v3); fma2(ap1[2 * c + 3], pp1, v3);
            }
        }
    }
    const float r0 = 1.f / l0;
    const float r1 = 1.f / l1;

    // ---- fp16 output, direct 16B stores (2 rows) ----
#pragma unroll
    for (int g = 0; g < 8; g++) {          // 8 dims per group = 4 packed pairs
        __half hv0[8], hv1[8];
#pragma unroll
        for (int e = 0; e < 4; e++) {
            float x0, x1, y0, y1;
            unpack2f(ap0[g * 4 + e], x0, x1);
            unpack2f(ap1[g * 4 + e], y0, y1);
            hv0[2 * e]     = __float2half(x0 * r0);
            hv0[2 * e + 1] = __float2half(x1 * r0);
            hv1[2 * e]     = __float2half(y0 * r1);
            hv1[2 * e + 1] = __float2half(y1 * r1);
        }
        *(uint4*)(o + base + (size_t)q0 * D_MODEL + g * 8) = *(uint4*)hv0;
        *(uint4*)(o + base + (size_t)q1 * D_MODEL + g * 8) = *(uint4*)hv1;
    }
}

// ---------------------------------------------------------------------------
extern "C" void kernel_launch(void* const* d_in, const int* in_sizes, int n_in,
                              void* d_out, int out_size)
{
    const float* x  = (const float*)d_in[0];
    const float* Wq = (const float*)d_in[1];
    const float* Wk = (const float*)d_in[2];
    const float* Wv = (const float*)d_in[3];
    const float* Wo = (const float*)d_in[4];
    float* out = (float*)d_out;

    float *q, *k, *v;
    __half *x_h, *att_h, *wt_h, *wt_l;
    cudaGetSymbolAddress((void**)&q, g_q);
    cudaGetSymbolAddress((void**)&k, g_k);
    cudaGetSymbolAddress((void**)&v, g_v);
    cudaGetSymbolAddress((void**)&x_h, g_x_h);
    cudaGetSymbolAddress((void**)&att_h, g_att_h);
    cudaGetSymbolAddress((void**)&wt_h, g_wt_h);
    cudaGetSymbolAddress((void**)&wt_l, g_wt_l);

    cudaFuncSetAttribute(gemm_mma_kernel,
                         cudaFuncAttributeMaxDynamicSharedMemorySize, GEMM_SMEM);
    cudaFuncSetAttribute(attn_kernel,
                         cudaFuncAttributeMaxDynamicSharedMemorySize, ATT_SMEM_BYTES);

    const size_t DD = (size_t)D_MODEL * D_MODEL;
    const int n4 = ROWS * D_MODEL / 4;

    // conversions: x -> fp16, fused 4-weight transpose + fp16 hi/lo of 32W
    split_h_kernel<<<(n4 + 255) / 256, 256>>>(x, x_h, n4);
    dim3 wgrid(32, 32, 4), wblk(32, 8);
    wsplit4_kernel<<<wgrid, wblk>>>(Wq, Wk, Wv, Wo, wt_h, wt_l);

    // fused QKV projection: B rows 0..3071 of wt (q,k,v contiguous)
    dim3 gqkv(3 * D_MODEL / 128, ROWS / 128);   // (24, 256)
    gemm_mma_kernel<<<gqkv, 256, GEMM_SMEM>>>(x_h, wt_h, wt_l, q, k, v);

    // attention: 256-query CTAs, 2 queries/thread, fp16 probs, fp16 output
    dim3 attn_grid(NH, NCHUNK, BATCH);          // (16, 32, 4)
    attn_kernel<<<attn_grid, 128, ATT_SMEM_BYTES>>>(q, k, v, att_h);

    // output projection
    dim3 go(D_MODEL / 128, ROWS / 128);
    gemm_mma_kernel<<<go, 256, GEMM_SMEM>>>(att_h, wt_h + 3 * DD, wt_l + 3 * DD,
                                            out, out, out);
}

// round 12
// speedup vs baseline: 2.4347x; 1.6064x over previous
#include <cuda_runtime.h>
#include <cuda_bf16.h>
#include <cuda_fp16.h>
#include <cstdint>

#define D_MODEL 1024
#define NH 16
#define HD 64
#define CHUNK 256
#define WIN 64
#define BATCH 4
#define SEQ 8192
#define NCHUNK (SEQ / CHUNK)
#define ROWS (BATCH * SEQ)

// Weights pre-scaled by 32 (keeps fp16 well in range); epilogue * 1/32.
#define WSCALE 32.0f
#define OSCALE (1.0f / 32.0f)

// ---------------- scratch (__device__ globals; no allocs allowed) ----------
__device__ float g_q[ROWS * D_MODEL];
__device__ float g_k[ROWS * D_MODEL];
__device__ float g_v[ROWS * D_MODEL];
__device__ __half g_x_h[ROWS * D_MODEL];     // fp16(x)
__device__ __half g_att_h[ROWS * D_MODEL];   // fp16(att)
// 4 transposed weights (q,k,v,o), fp16 of 32*W, [N=1024][K=1024] K-major
__device__ __half g_wt_h[4 * D_MODEL * D_MODEL];

// ---------------------------------------------------------------------------
// helpers
// ---------------------------------------------------------------------------
__device__ __forceinline__ uint32_t smem_u32(const void* p) {
    uint32_t a;
    asm("{ .reg .u64 t; cvta.to.shared.u64 t, %1; cvt.u32.u64 %0, t; }"
        : "=r"(a) : "l"(p));
    return a;
}

__device__ __forceinline__ void cp_async16(uint32_t dst, const void* src) {
    asm volatile("cp.async.cg.shared.global [%0], [%1], 16;"
                 :: "r"(dst), "l"(src) : "memory");
}
__device__ __forceinline__ void cp_commit() {
    asm volatile("cp.async.commit_group;" ::: "memory");
}
__device__ __forceinline__ void cp_wait1() {
    asm volatile("cp.async.wait_group 1;" ::: "memory");
}

__device__ __forceinline__ void ldsm_x4(uint32_t* r, uint32_t addr) {
    asm volatile("ldmatrix.sync.aligned.m8n8.x4.shared.b16 {%0,%1,%2,%3}, [%4];"
                 : "=r"(r[0]), "=r"(r[1]), "=r"(r[2]), "=r"(r[3]) : "r"(addr));
}

// fp16 mma, fp32 accumulate
__device__ __forceinline__ void mma16816h(float* c, const uint32_t* a, const uint32_t* b) {
    asm volatile(
        "mma.sync.aligned.m16n8k16.row.col.f32.f16.f16.f32 "
        "{%0,%1,%2,%3}, {%4,%5,%6,%7}, {%8,%9}, {%0,%1,%2,%3};"
        : "+f"(c[0]), "+f"(c[1]), "+f"(c[2]), "+f"(c[3])
        : "r"(a[0]), "r"(a[1]), "r"(a[2]), "r"(a[3]), "r"(b[0]), "r"(b[1]));
}

// ---- packed f32x2 ops (FFMA2 path, PTX-only per SASS_QUICKREF) ----
__device__ __forceinline__ uint64_t pack2f(float lo, float hi) {
    uint64_t r;
    asm("mov.b64 %0, {%1,%2};" : "=l"(r) : "f"(lo), "f"(hi));
    return r;
}
__device__ __forceinline__ void unpack2f(uint64_t p, float& lo, float& hi) {
    asm("mov.b64 {%0,%1}, %2;" : "=f"(lo), "=f"(hi) : "l"(p));
}
__device__ __forceinline__ void fma2(uint64_t& d, uint64_t a, uint64_t b) {
    asm("fma.rn.f32x2 %0, %1, %2, %0;" : "+l"(d) : "l"(a), "l"(b));
}
__device__ __forceinline__ uint64_t mul2(uint64_t a, uint64_t b) {
    uint64_t r;
    asm("mul.rn.f32x2 %0, %1, %2;" : "=l"(r) : "l"(a), "l"(b));
    return r;
}
__device__ __forceinline__ uint64_t add2(uint64_t a, uint64_t b) {
    uint64_t r;
    asm("add.rn.f32x2 %0, %1, %2;" : "=l"(r) : "l"(a), "l"(b));
    return r;
}
__device__ __forceinline__ void lds_v2u64(uint64_t& a, uint64_t& b, uint32_t addr) {
    asm volatile("ld.shared.v2.b64 {%0,%1}, [%2];" : "=l"(a), "=l"(b) : "r"(addr));
}

// ---------------------------------------------------------------------------
// GEMM tile geometry: 128 rows x 64 fp16 cols = 128B rows, 8x 16B chunks/row,
// chunk swizzle c' = c ^ (r & 7).
// ---------------------------------------------------------------------------
#define TILE_B 16384           // one 128x64 fp16 tile
#define STAGE_B (2 * TILE_B)   // A, B
#define NSTAGE 3
#define GEMM_SMEM (NSTAGE * STAGE_B)  // 98304
#define KIT 16                 // 1024 / 64

__device__ __forceinline__ uint32_t sw128(uint32_t tile_base, int r, int c) {
    return tile_base + r * 128 + (((c) ^ (r & 7)) << 4);
}

// ---------------------------------------------------------------------------
// fp32 -> fp16 for activations
// ---------------------------------------------------------------------------
__global__ __launch_bounds__(256) void split_h_kernel(
    const float* __restrict__ in, __half* __restrict__ out, int n4)
{
    int i = blockIdx.x * blockDim.x + threadIdx.x;
    if (i >= n4) return;
    float4 x = ((const float4*)in)[i];
    __half h[4] = {__float2half(x.x), __float2half(x.y),
                   __float2half(x.z), __float2half(x.w)};
    *(uint2*)(out + 4 * (size_t)i) = *(uint2*)h;
}

// Fused weight transpose + fp16 of 32*W for all 4 weights (grid.z selects)
__global__ __launch_bounds__(256) void wsplit4_kernel(
    const float* __restrict__ W0, const float* __restrict__ W1,
    const float* __restrict__ W2, const float* __restrict__ W3,
    __half* __restrict__ hT)
{
    __shared__ float tile[32][33];
    const int z = blockIdx.z;
    const float* W = (z == 0) ? W0 : (z == 1) ? W1 : (z == 2) ? W2 : W3;
    const size_t off = (size_t)z * D_MODEL * D_MODEL;
    int bx = blockIdx.x * 32, by = blockIdx.y * 32;
    int tx = threadIdx.x, ty = threadIdx.y;  // 32x8
#pragma unroll
    for (int r = ty; r < 32; r += 8)
        tile[r][tx] = W[(size_t)(by + r) * D_MODEL + bx + tx];
    __syncthreads();
#pragma unroll
    for (int r = ty; r < 32; r += 8) {
        float v = tile[tx][r] * WSCALE;  // = 32 * W[(by+tx)*D + bx+r]
        hT[off + (size_t)(bx + r) * D_MODEL + by + tx] = __float2half(v);
    }
}

// ---------------------------------------------------------------------------
// Single-pass fp16 GEMM via mma.sync: C = (1/32) * A_fp16 @ B^T, fp32 acc.
// B = fp16(32*W), K-major, pre-transposed. CTA 128x128, BK=64,
// 3-stage cp.async pipeline (32KB/stage), 8 warps (2m x 4n), 2 CTAs/SM,
// 16 mainloop iterations (half the barrier count of BK=32).
// Multi-output: C[blockIdx.x >> 3] for fused QKV.
// ---------------------------------------------------------------------------
__global__ __launch_bounds__(256, 2) void gemm_mma_kernel(
    const __half* __restrict__ A, const __half* __restrict__ B,
    float* __restrict__ C0, float* __restrict__ C1, float* __restrict__ C2)
{
    extern __shared__ char smem[];
    const uint32_t sbase = smem_u32(smem);
    const int tid = threadIdx.x;
    const int lane = tid & 31;
    const int wid = tid >> 5;
    const int wm = wid >> 2;        // 0..1
    const int wn = wid & 3;         // 0..3
    const int m0 = blockIdx.y * 128;
    const int nB = blockIdx.x * 128;        // row in the B (weight) matrix
    const int w = nB >> 10;
    const int col0 = nB & 1023;
    float* __restrict__ C = (w == 0) ? C0 : (w == 1) ? C1 : C2;

    auto load_stage = [&](int stage, int k0) {
        uint32_t sb = sbase + stage * STAGE_B;
#pragma unroll
        for (int i = 0; i < 8; i++) {
            int cid = tid + i * 256;       // 0..2047
            int t = cid >> 10;             // 0=A, 1=B
            int e = cid & 1023;
            int r = e >> 3;                // 0..127
            int c = e & 7;                 // 16B chunk
            const __half* s = t ? B : A;
            int row0 = t ? nB : m0;
            const void* g = s + (size_t)(row0 + r) * D_MODEL + k0 + c * 8;
            cp_async16(sw128(sb + t * TILE_B, r, c), g);
        }
    };

    float acc[4][4][4];
#pragma unroll
    for (int i = 0; i < 4; i++)
#pragma unroll
        for (int j = 0; j < 4; j++)
#pragma unroll
            for (int e = 0; e < 4; e++) acc[i][j][e] = 0.f;

    load_stage(0, 0);
    cp_commit();
    load_stage(1, 64);
    cp_commit();

    const int a_r = lane & 15;
    const int a_c = lane >> 4;
    const int b_r = (lane & 7) + ((lane >> 4) << 3);
    const int b_c = (lane >> 3) & 1;

    for (int it = 0; it < KIT; it++) {
        cp_wait1();
        __syncthreads();           // stage it visible; compute(it-1) done CTA-wide
        if (it + 2 < KIT) load_stage((it + 2) % NSTAGE, (it + 2) * 64);
        cp_commit();

        const uint32_t sb = sbase + (it % NSTAGE) * STAGE_B;
        const uint32_t tA = sb;
        const uint32_t tB = sb + TILE_B;

#pragma unroll
        for (int ks = 0; ks < 4; ks++) {   // 4 x k16 within BK=64
            uint32_t a[4][4], bf[4][2];
#pragma unroll
            for (int mt = 0; mt < 4; mt++) {
                int r = wm * 64 + mt * 16 + a_r;
                ldsm_x4(a[mt], sw128(tA, r, ks * 2 + a_c));
            }
#pragma unroll
            for (int np = 0; np < 2; np++) {
                uint32_t t4[4];
                int r = wn * 32 + np * 16 + b_r;
                ldsm_x4(t4, sw128(tB, r, ks * 2 + b_c));
                bf[np * 2][0] = t4[0]; bf[np * 2][1] = t4[1];
                bf[np * 2 + 1][0] = t4[2]; bf[np * 2 + 1][1] = t4[3];
            }
#pragma unroll
            for (int mt = 0; mt < 4; mt++)
#pragma unroll
                for (int nt = 0; nt < 4; nt++)
                    mma16816h(acc[mt][nt], a[mt], bf[nt]);
        }
    }

    const int er = lane >> 2;
    const int ec = (lane & 3) * 2;
#pragma unroll
    for (int mt = 0; mt < 4; mt++) {
#pragma unroll
        for (int nt = 0; nt < 4; nt++) {
            int row = m0 + wm * 64 + mt * 16 + er;
            int col = col0 + wn * 32 + nt * 8 + ec;
            *(float2*)(C + (size_t)row * D_MODEL + col) =
                make_float2(acc[mt][nt][0] * OSCALE, acc[mt][nt][1] * OSCALE);
            *(float2*)(C + (size_t)(row + 8) * D_MODEL + col) =
                make_float2(acc[mt][nt][2] * OSCALE, acc[mt][nt][3] * OSCALE);
        }
    }
}

// ---------------------------------------------------------------------------
// Banded chunk-local attention (unchanged from R11): 256-query CTA,
// 128 threads, 2 adjacent queries/thread, fused score+exp, fp16 probs,
// fp16 output. 2 CTAs/SM.
// ---------------------------------------------------------------------------
#define ATT_SC 67
#define ATT_SMEM_BYTES (CHUNK * 64 * 4 + CHUNK * ATT_SC * 2)  // 99840

__device__ __forceinline__ int att_addr(int r, int c) {
    return r * 64 + ((c ^ ((r >> 1) & 7)) << 2);
}

__device__ __forceinline__ void att_load_tile(
    float* __restrict__ buf, const float* __restrict__ src, size_t base, int tid)
{
#pragma unroll
    for (int i = 0; i < 32; i++) {
        int idx = tid + i * 128;
        int r = idx >> 4;
        int c = idx & 15;
        float4 t = *(const float4*)(src + base + (size_t)r * D_MODEL + c * 4);
        *(float4*)(buf + att_addr(r, c)) = t;
    }
}

__global__ __launch_bounds__(128) void attn_kernel(
    const float* __restrict__ q, const float* __restrict__ k,
    const float* __restrict__ v, __half* __restrict__ o)
{
    extern __shared__ float fsmem[];
    float* buf = fsmem;
    __half* sc = (__half*)(fsmem + CHUNK * 64);
    const uint32_t sb = smem_u32(fsmem);

    const int h = blockIdx.x;
    const int n = blockIdx.y;
    const int b = blockIdx.z;
    const int t = threadIdx.x;
    const int q0 = 2 * t;
    const int q1 = 2 * t + 1;

    const size_t base = ((size_t)(b * SEQ + n * CHUNK)) * D_MODEL + h * HD;

    att_load_tile(buf, q, base, t);
    __syncthreads();
    uint64_t qp0[32], qp1[32];
    {
        const uint64_t scale2 = pack2f(0.125f, 0.125f);
#pragma unroll
        for (int c = 0; c < 16; c++) {
            uint64_t a, bq;
            lds_v2u64(a, bq, sb + 4 * att_addr(q0, c));
            qp0[2 * c] = mul2(a, scale2); qp0[2 * c + 1] = mul2(bq, scale2);
            lds_v2u64(a, bq, sb + 4 * att_addr(q1, c));
            qp1[2 * c] = mul2(a, scale2); qp1[2 * c + 1] = mul2(bq, scale2);
        }
    }
    __syncthreads();

    att_load_tile(buf, k, base, t);
    __syncthreads();

    const uint64_t zero2 = pack2f(0.f, 0.f);
    float l0 = 0.f, l1 = 0.f;
#pragma unroll 2
    for (int ju = 0; ju <= 65; ju++) {
        int j = q0 - 64 + ju;
        float p0f = 0.f, p1f = 0.f;
        if (j >= 0) {
            uint64_t a0a = zero2, a0b = zero2, a1a = zero2, a1b = zero2;
#pragma unroll
            for (int c = 0; c < 16; c += 2) {
                uint64_t k0, k1, k2, k3;
                lds_v2u64(k0, k1, sb + 4 * att_addr(j, c));
                lds_v2u64(k2, k3, sb + 4 * att_addr(j, c + 1));
                fma2(a0a, qp0[2 * c], k0);     fma2(a1a, qp1[2 * c], k0);
                fma2(a0b, qp0[2 * c + 1], k1); fma2(a1b, qp1[2 * c + 1], k1);
                fma2(a0a, qp0[2 * c + 2], k2); fma2(a1a, qp1[2 * c + 2], k2);
                fma2(a0b, qp0[2 * c + 3], k3); fma2(a1b, qp1[2 * c + 3], k3);
            }
            uint64_t t0 = add2(a0a, a0b);
            uint64_t t1 = add2(a1a, a1b);
            float e0, o0, e1, o1;
            unpack2f(t0, e0, o0);
            unpack2f(t1, e1, o1);
            if (ju <= 64) p0f = __expf(e0 + o0);
            if (ju >= 1)  p1f = __expf(e1 + o1);
        }
        __half h0 = __float2half(p0f);
        __half h1 = __float2half(p1f);
        l0 += __half2float(h0);
        l1 += __half2float(h1);
        sc[q0 * ATT_SC + ju] = h0;
        sc[q1 * ATT_SC + ju] = h1;
    }
    __syncthreads();

    att_load_tile(buf, v, base, t);
    __syncthreads();

    uint64_t ap0[32], ap1[32];
#pragma unroll
    for (int i = 0; i < 32; i++) { ap0[i] = zero2; ap1[i] = zero2; }
#pragma unroll 2
    for (int ju = 0; ju <= 65; ju++) {
        int j = q0 - 64 + ju;
        if (j >= 0) {
            float p0 = __half2float(sc[q0 * ATT_SC + ju]);
            float p1 = __half2float(sc[q1 * ATT_SC + ju]);
            uint64_t pp0 = pack2f(p0, p0);
            uint64_t pp1 = pack2f(p1, p1);
#pragma unroll
            for (int c = 0; c < 16; c += 2) {
                uint64_t v0, v1, v2, v3;
                lds_v2u64(v0, v1, sb + 4 * att_addr(j, c));
                lds_v2u64(v2, v3, sb + 4 * att_addr(j, c + 1));
                fma2(ap0[2 * c], pp0, v0);     fma2(ap1[2 * c], pp1, v0);
                fma2(ap0[2 * c + 1], pp0, v1); fma2(ap1[2 * c + 1], pp1, v1);
                fma2(ap0[2 * c + 2], pp0, v2); fma2(ap1[2 * c + 2], pp1, v2);
                fma2(ap0[2 * c + 3], pp0, v3); fma2(ap1[2 * c + 3], pp1, v3);
            }
        }
    }
    const float r0 = 1.f / l0;
    const float r1 = 1.f / l1;

#pragma unroll
    for (int g = 0; g < 8; g++) {
        __half hv0[8], hv1[8];
#pragma unroll
        for (int e = 0; e < 4; e++) {
            float x0, x1, y0, y1;
            unpack2f(ap0[g * 4 + e], x0, x1);
            unpack2f(ap1[g * 4 + e], y0, y1);
            hv0[2 * e]     = __float2half(x0 * r0);
            hv0[2 * e + 1] = __float2half(x1 * r0);
            hv1[2 * e]     = __float2half(y0 * r1);
            hv1[2 * e + 1] = __float2half(y1 * r1);
        }
        *(uint4*)(o + base + (size_t)q0 * D_MODEL + g * 8) = *(uint4*)hv0;
        *(uint4*)(o + base + (size_t)q1 * D_MODEL + g * 8) = *(uint4*)hv1;
    }
}

// ---------------------------------------------------------------------------
extern "C" void kernel_launch(void* const* d_in, const int* in_sizes, int n_in,
                              void* d_out, int out_size)
{
    const float* x  = (const float*)d_in[0];
    const float* Wq = (const float*)d_in[1];
    const float* Wk = (const float*)d_in[2];
    const float* Wv = (const float*)d_in[3];
    const float* Wo = (const float*)d_in[4];
    float* out = (float*)d_out;

    float *q, *k, *v;
    __half *x_h, *att_h, *wt_h;
    cudaGetSymbolAddress((void**)&q, g_q);
    cudaGetSymbolAddress((void**)&k, g_k);
    cudaGetSymbolAddress((void**)&v, g_v);
    cudaGetSymbolAddress((void**)&x_h, g_x_h);
    cudaGetSymbolAddress((void**)&att_h, g_att_h);
    cudaGetSymbolAddress((void**)&wt_h, g_wt_h);

    cudaFuncSetAttribute(gemm_mma_kernel,
                         cudaFuncAttributeMaxDynamicSharedMemorySize, GEMM_SMEM);
    cudaFuncSetAttribute(attn_kernel,
                         cudaFuncAttributeMaxDynamicSharedMemorySize, ATT_SMEM_BYTES);

    const size_t DD = (size_t)D_MODEL * D_MODEL;
    const int n4 = ROWS * D_MODEL / 4;

    // conversions
    split_h_kernel<<<(n4 + 255) / 256, 256>>>(x, x_h, n4);
    dim3 wgrid(32, 32, 4), wblk(32, 8);
    wsplit4_kernel<<<wgrid, wblk>>>(Wq, Wk, Wv, Wo, wt_h);

    // fused QKV projection (single-pass fp16)
    dim3 gqkv(3 * D_MODEL / 128, ROWS / 128);   // (24, 256)
    gemm_mma_kernel<<<gqkv, 256, GEMM_SMEM>>>(x_h, wt_h, q, k, v);

    // attention
    dim3 attn_grid(NH, NCHUNK, BATCH);          // (16, 32, 4)
    attn_kernel<<<attn_grid, 128, ATT_SMEM_BYTES>>>(q, k, v, att_h);

    // output projection (single-pass fp16)
    dim3 go(D_MODEL / 128, ROWS / 128);
    gemm_mma_kernel<<<go, 256, GEMM_SMEM>>>(att_h, wt_h + 3 * DD, out, out, out);
}

// round 13
// speedup vs baseline: 3.3617x; 1.3807x over previous
#include <cuda_runtime.h>
#include <cuda_bf16.h>
#include <cuda_fp16.h>
#include <cstdint>

#define D_MODEL 1024
#define NH 16
#define HD 64
#define CHUNK 256
#define WIN 64
#define BATCH 4
#define SEQ 8192
#define NCHUNK (SEQ / CHUNK)
#define ROWS (BATCH * SEQ)

// Weights pre-scaled by 32; epilogue * 1/32. Q additionally * 1/8 (attn scale).
#define WSCALE 32.0f
#define OSCALE (1.0f / 32.0f)

// ---------------- scratch (__device__ globals; no allocs allowed) ----------
__device__ __half g_q_h[ROWS * D_MODEL];     // fp16(q/8)
__device__ __half g_k_h[ROWS * D_MODEL];     // fp16(k)
__device__ __half g_v_h[ROWS * D_MODEL];     // fp16(v)
__device__ __half g_x_h[ROWS * D_MODEL];     // fp16(x)
__device__ __half g_att_h[ROWS * D_MODEL];   // fp16(att)
__device__ __half g_wt_h[4 * D_MODEL * D_MODEL];  // fp16(32*W^T), K-major

// ---------------------------------------------------------------------------
// helpers
// ---------------------------------------------------------------------------
__device__ __forceinline__ uint32_t smem_u32(const void* p) {
    uint32_t a;
    asm("{ .reg .u64 t; cvta.to.shared.u64 t, %1; cvt.u32.u64 %0, t; }"
        : "=r"(a) : "l"(p));
    return a;
}
__device__ __forceinline__ void cp_async16(uint32_t dst, const void* src) {
    asm volatile("cp.async.cg.shared.global [%0], [%1], 16;"
                 :: "r"(dst), "l"(src) : "memory");
}
__device__ __forceinline__ void cp_commit() {
    asm volatile("cp.async.commit_group;" ::: "memory");
}
__device__ __forceinline__ void cp_wait1() {
    asm volatile("cp.async.wait_group 1;" ::: "memory");
}
__device__ __forceinline__ void cp_wait0() {
    asm volatile("cp.async.wait_group 0;" ::: "memory");
}
__device__ __forceinline__ void ldsm_x4(uint32_t* r, uint32_t addr) {
    asm volatile("ldmatrix.sync.aligned.m8n8.x4.shared.b16 {%0,%1,%2,%3}, [%4];"
                 : "=r"(r[0]), "=r"(r[1]), "=r"(r[2]), "=r"(r[3]) : "r"(addr));
}
__device__ __forceinline__ void ldsm_x4_t(uint32_t* r, uint32_t addr) {
    asm volatile("ldmatrix.sync.aligned.m8n8.x4.trans.shared.b16 {%0,%1,%2,%3}, [%4];"
                 : "=r"(r[0]), "=r"(r[1]), "=r"(r[2]), "=r"(r[3]) : "r"(addr));
}
__device__ __forceinline__ void mma16816h(float* c, const uint32_t* a, const uint32_t* b) {
    asm volatile(
        "mma.sync.aligned.m16n8k16.row.col.f32.f16.f16.f32 "
        "{%0,%1,%2,%3}, {%4,%5,%6,%7}, {%8,%9}, {%0,%1,%2,%3};"
        : "+f"(c[0]), "+f"(c[1]), "+f"(c[2]), "+f"(c[3])
        : "r"(a[0]), "r"(a[1]), "r"(a[2]), "r"(a[3]), "r"(b[0]), "r"(b[1]));
}

// 128B fp16 rows (64 halfs), 8x 16B chunks, swizzle c' = c ^ (r & 7)
__device__ __forceinline__ uint32_t hsw(uint32_t tile_base, int r, int c) {
    return tile_base + r * 128 + (((c) ^ (r & 7)) << 4);
}

// ---------------------------------------------------------------------------
// conversions
// ---------------------------------------------------------------------------
__global__ __launch_bounds__(256) void split_h_kernel(
    const float* __restrict__ in, __half* __restrict__ out, int n4)
{
    int i = blockIdx.x * blockDim.x + threadIdx.x;
    if (i >= n4) return;
    float4 x = ((const float4*)in)[i];
    __half h[4] = {__float2half(x.x), __float2half(x.y),
                   __float2half(x.z), __float2half(x.w)};
    *(uint2*)(out + 4 * (size_t)i) = *(uint2*)h;
}

__global__ __launch_bounds__(256) void wsplit4_kernel(
    const float* __restrict__ W0, const float* __restrict__ W1,
    const float* __restrict__ W2, const float* __restrict__ W3,
    __half* __restrict__ hT)
{
    __shared__ float tile[32][33];
    const int z = blockIdx.z;
    const float* W = (z == 0) ? W0 : (z == 1) ? W1 : (z == 2) ? W2 : W3;
    const size_t off = (size_t)z * D_MODEL * D_MODEL;
    int bx = blockIdx.x * 32, by = blockIdx.y * 32;
    int tx = threadIdx.x, ty = threadIdx.y;
#pragma unroll
    for (int r = ty; r < 32; r += 8)
        tile[r][tx] = W[(size_t)(by + r) * D_MODEL + bx + tx];
    __syncthreads();
#pragma unroll
    for (int r = ty; r < 32; r += 8) {
        float v = tile[tx][r] * WSCALE;
        hT[off + (size_t)(bx + r) * D_MODEL + by + tx] = __float2half(v);
    }
}

// ---------------------------------------------------------------------------
// Single-pass fp16 GEMM (BK=64, 3-stage cp.async, 8 warps, 2 CTAs/SM).
// HALF_OUT: fp16 epilogue (QKV path, per-output scale). Else fp32 (O path).
// ---------------------------------------------------------------------------
#define TILE_B 16384
#define STAGE_B (2 * TILE_B)
#define NSTAGE 3
#define GEMM_SMEM (NSTAGE * STAGE_B)  // 98304
#define KIT 16

template <bool HALF_OUT>
__global__ __launch_bounds__(256, 2) void gemm_mma_kernel(
    const __half* __restrict__ A, const __half* __restrict__ B,
    void* __restrict__ C0v, void* __restrict__ C1v, void* __restrict__ C2v,
    float s0, float s1, float s2)
{
    extern __shared__ char smem[];
    const uint32_t sbase = smem_u32(smem);
    const int tid = threadIdx.x;
    const int lane = tid & 31;
    const int wid = tid >> 5;
    const int wm = wid >> 2;
    const int wn = wid & 3;
    const int m0 = blockIdx.y * 128;
    const int nB = blockIdx.x * 128;
    const int w = nB >> 10;
    const int col0 = nB & 1023;
    void* Cv = (w == 0) ? C0v : (w == 1) ? C1v : C2v;
    const float sc = (w == 0) ? s0 : (w == 1) ? s1 : s2;

    auto load_stage = [&](int stage, int k0) {
        uint32_t sb = sbase + stage * STAGE_B;
#pragma unroll
        for (int i = 0; i < 8; i++) {
            int cid = tid + i * 256;
            int t = cid >> 10;
            int e = cid & 1023;
            int r = e >> 3;
            int c = e & 7;
            const __half* s = t ? B : A;
            int row0 = t ? nB : m0;
            const void* g = s + (size_t)(row0 + r) * D_MODEL + k0 + c * 8;
            cp_async16(hsw(sb + t * TILE_B, r, c), g);
        }
    };

    float acc[4][4][4];
#pragma unroll
    for (int i = 0; i < 4; i++)
#pragma unroll
        for (int j = 0; j < 4; j++)
#pragma unroll
            for (int e = 0; e < 4; e++) acc[i][j][e] = 0.f;

    load_stage(0, 0);
    cp_commit();
    load_stage(1, 64);
    cp_commit();

    for (int it = 0; it < KIT; it++) {
        cp_wait1();
        __syncthreads();
        if (it + 2 < KIT) load_stage((it + 2) % NSTAGE, (it + 2) * 64);
        cp_commit();

        const uint32_t sb = sbase + (it % NSTAGE) * STAGE_B;
        const uint32_t tA = sb;
        const uint32_t tB = sb + TILE_B;

#pragma unroll
        for (int ks = 0; ks < 4; ks++) {
            uint32_t a[4][4], bf[4][2];
#pragma unroll
            for (int mt = 0; mt < 4; mt++) {
                int r = wm * 64 + mt * 16 + (lane & 15);
                ldsm_x4(a[mt], hsw(tA, r, ks * 2 + (lane >> 4)));
            }
#pragma unroll
            for (int np = 0; np < 2; np++) {
                uint32_t t4[4];
                int r = wn * 32 + np * 16 + (lane & 7) + ((lane >> 4) << 3);
                ldsm_x4(t4, hsw(tB, r, ks * 2 + ((lane >> 3) & 1)));
                bf[np * 2][0] = t4[0]; bf[np * 2][1] = t4[1];
                bf[np * 2 + 1][0] = t4[2]; bf[np * 2 + 1][1] = t4[3];
            }
#pragma unroll
            for (int mt = 0; mt < 4; mt++)
#pragma unroll
                for (int nt = 0; nt < 4; nt++)
                    mma16816h(acc[mt][nt], a[mt], bf[nt]);
        }
    }

    const int er = lane >> 2;
    const int ec = (lane & 3) * 2;
#pragma unroll
    for (int mt = 0; mt < 4; mt++) {
#pragma unroll
        for (int nt = 0; nt < 4; nt++) {
            int row = m0 + wm * 64 + mt * 16 + er;
            int col = col0 + wn * 32 + nt * 8 + ec;
            if (HALF_OUT) {
                __half* C = (__half*)Cv;
                __half2 h0 = __floats2half2_rn(acc[mt][nt][0] * sc, acc[mt][nt][1] * sc);
                __half2 h1 = __floats2half2_rn(acc[mt][nt][2] * sc, acc[mt][nt][3] * sc);
                *(__half2*)(C + (size_t)row * D_MODEL + col) = h0;
                *(__half2*)(C + (size_t)(row + 8) * D_MODEL + col) = h1;
            } else {
                float* C = (float*)Cv;
                *(float2*)(C + (size_t)row * D_MODEL + col) =
                    make_float2(acc[mt][nt][0] * sc, acc[mt][nt][1] * sc);
                *(float2*)(C + (size_t)(row + 8) * D_MODEL + col) =
                    make_float2(acc[mt][nt][2] * sc, acc[mt][nt][3] * sc);
            }
        }
    }
}

// ---------------------------------------------------------------------------
// Tensor-core banded attention. CTA = (head, chunk, batch), 8 warps.
// Warp owns 32 query rows (2 m16 tiles). Per m16 tile the band spans exactly
// 10 n8 key-tiles (16-aligned, negative tiles skipped in pairs).
// S = Q@K^T via mma (Q pre-scaled 1/8), exp in fragment regs (no max-sub:
// |s|<=8), P stays in registers (C-frag == A-frag layout for PV),
// V B-frags via ldmatrix.trans, row sums via quad shfl. fp16 in/out.
// smem: q,k,v tiles 3 x 32KB = 96KB -> 2 CTAs/SM.
// ---------------------------------------------------------------------------
#define ATT_SMEM (3 * 32768)

__global__ __launch_bounds__(256, 2) void attn_mma_kernel(
    const __half* __restrict__ q, const __half* __restrict__ k,
    const __half* __restrict__ v, __half* __restrict__ o)
{
    extern __shared__ char smem[];
    const uint32_t sb = smem_u32(smem);
    const int tid = threadIdx.x;
    const int lane = tid & 31;
    const int warp = tid >> 5;
    const int h = blockIdx.x, n = blockIdx.y, b = blockIdx.z;
    const size_t base = ((size_t)(b * SEQ + n * CHUNK)) * D_MODEL + h * HD;

    // ---- stage q,k,v (each 256x64 fp16, swizzled) ----
    {
        const __half* srcs[3] = {q, k, v};
#pragma unroll
        for (int i = 0; i < 24; i++) {
            int idx = tid + i * 256;       // 0..6143
            int t = idx >> 11;
            int e = idx & 2047;
            int r = e >> 3, c = e & 7;
            const void* g = srcs[t] + base + (size_t)r * D_MODEL + c * 8;
            cp_async16(hsw(sb + t * 32768, r, c), g);
        }
        cp_commit();
        cp_wait0();
        __syncthreads();
    }

    const uint32_t sQ = sb, sK = sb + 32768, sV = sb + 65536;
    const int lr = lane >> 2;    // 0..7
    const int lc = lane & 3;

#pragma unroll
    for (int mt = 0; mt < 2; mt++) {
        const int r0 = warp * 32 + mt * 16;

        // Q A-frags (m16 x k64)
        uint32_t qa[4][4];
#pragma unroll
        for (int kk = 0; kk < 4; kk++)
            ldsm_x4(qa[kk], hsw(sQ, r0 + (lane & 15), kk * 2 + (lane >> 4)));

        const int st = (r0 >> 3) - 8;      // first band tile (even, may be <0)
        uint32_t pa[5][4];
        float sum0 = 0.f, sum1 = 0.f;

#pragma unroll
        for (int p = 0; p < 5; p++) {
            int t0 = st + 2 * p;
            if (t0 < 0) continue;          // warp-uniform
            float c0f[4] = {0.f, 0.f, 0.f, 0.f};
            float c1f[4] = {0.f, 0.f, 0.f, 0.f};
#pragma unroll
            for (int kk = 0; kk < 4; kk++) {
                uint32_t r4[4];
                ldsm_x4(r4, hsw(sK, 8 * t0 + (lane & 15), kk * 2 + (lane >> 4)));
                uint32_t b0[2] = {r4[0], r4[2]};
                uint32_t b1[2] = {r4[1], r4[3]};
                mma16816h(c0f, qa[kk], b0);
                mma16816h(c1f, qa[kk], b1);
            }
            const int row0 = r0 + lr, row1 = row0 + 8;
            const int col = 8 * t0 + 2 * lc;
            float e0 = (col     >= row0 - 64 && col     <= row0) ? __expf(c0f[0]) : 0.f;
            float e1 = (col + 1 >= row0 - 64 && col + 1 <= row0) ? __expf(c0f[1]) : 0.f;
            float e2 = (col     >= row1 - 64 && col     <= row1) ? __expf(c0f[2]) : 0.f;
            float e3 = (col + 1 >= row1 - 64 && col + 1 <= row1) ? __expf(c0f[3]) : 0.f;
            float e4 = (col + 8 >= row0 - 64 && col + 8 <= row0) ? __expf(c1f[0]) : 0.f;
            float e5 = (col + 9 >= row0 - 64 && col + 9 <= row0) ? __expf(c1f[1]) : 0.f;
            float e6 = (col + 8 >= row1 - 64 && col + 8 <= row1) ? __expf(c1f[2]) : 0.f;
            float e7 = (col + 9 >= row1 - 64 && col + 9 <= row1) ? __expf(c1f[3]) : 0.f;
            sum0 += e0 + e1 + e4 + e5;
            sum1 += e2 + e3 + e6 + e7;
            __half2 p0 = __floats2half2_rn(e0, e1);
            __half2 p1 = __floats2half2_rn(e2, e3);
            __half2 p2 = __floats2half2_rn(e4, e5);
            __half2 p3 = __floats2half2_rn(e6, e7);
            pa[p][0] = *(uint32_t*)&p0;    // a0: (row lr,  k 2lc..)
            pa[p][1] = *(uint32_t*)&p1;    // a1: (row lr+8)
            pa[p][2] = *(uint32_t*)&p2;    // a2: (row lr,  k+8)
            pa[p][3] = *(uint32_t*)&p3;    // a3: (row lr+8, k+8)
        }
        // full row sums across the quad
        sum0 += __shfl_xor_sync(0xffffffffu, sum0, 1);
        sum0 += __shfl_xor_sync(0xffffffffu, sum0, 2);
        sum1 += __shfl_xor_sync(0xffffffffu, sum1, 1);
        sum1 += __shfl_xor_sync(0xffffffffu, sum1, 2);

        // ---- P @ V ----
        float acc[8][4];
#pragma unroll
        for (int i = 0; i < 8; i++)
#pragma unroll
            for (int e = 0; e < 4; e++) acc[i][e] = 0.f;
#pragma unroll
        for (int p = 0; p < 5; p++) {
            int t0 = st + 2 * p;
            if (t0 < 0) continue;
            int k0 = 8 * t0;
#pragma unroll
            for (int nt2 = 0; nt2 < 4; nt2++) {
                uint32_t r4[4];
                ldsm_x4_t(r4, hsw(sV, k0 + (lane & 15), nt2 * 2 + (lane >> 4)));
                uint32_t b0[2] = {r4[0], r4[1]};
                uint32_t b1[2] = {r4[2], r4[3]};
                mma16816h(acc[2 * nt2], pa[p], b0);
                mma16816h(acc[2 * nt2 + 1], pa[p], b1);
            }
        }
        const float ri0 = 1.f / sum0;
        const float ri1 = 1.f / sum1;
        const int row0 = r0 + lr;
#pragma unroll
        for (int nt = 0; nt < 8; nt++) {
            __half2 h0 = __floats2half2_rn(acc[nt][0] * ri0, acc[nt][1] * ri0);
            __half2 h1 = __floats2half2_rn(acc[nt][2] * ri1, acc[nt][3] * ri1);
            *(__half2*)(o + base + (size_t)row0 * D_MODEL + nt * 8 + 2 * lc) = h0;
            *(__half2*)(o + base + (size_t)(row0 + 8) * D_MODEL + nt * 8 + 2 * lc) = h1;
        }
    }
}

// ---------------------------------------------------------------------------
extern "C" void kernel_launch(void* const* d_in, const int* in_sizes, int n_in,
                              void* d_out, int out_size)
{
    const float* x  = (const float*)d_in[0];
    const float* Wq = (const float*)d_in[1];
    const float* Wk = (const float*)d_in[2];
    const float* Wv = (const float*)d_in[3];
    const float* Wo = (const float*)d_in[4];
    float* out = (float*)d_out;

    __half *q_h, *k_h, *v_h, *x_h, *att_h, *wt_h;
    cudaGetSymbolAddress((void**)&q_h, g_q_h);
    cudaGetSymbolAddress((void**)&k_h, g_k_h);
    cudaGetSymbolAddress((void**)&v_h, g_v_h);
    cudaGetSymbolAddress((void**)&x_h, g_x_h);
    cudaGetSymbolAddress((void**)&att_h, g_att_h);
    cudaGetSymbolAddress((void**)&wt_h, g_wt_h);

    cudaFuncSetAttribute(gemm_mma_kernel<true>,
                         cudaFuncAttributeMaxDynamicSharedMemorySize, GEMM_SMEM);
    cudaFuncSetAttribute(gemm_mma_kernel<false>,
                         cudaFuncAttributeMaxDynamicSharedMemorySize, GEMM_SMEM);
    cudaFuncSetAttribute(attn_mma_kernel,
                         cudaFuncAttributeMaxDynamicSharedMemorySize, ATT_SMEM);

    const size_t DD = (size_t)D_MODEL * D_MODEL;
    const int n4 = ROWS * D_MODEL / 4;

    // conversions
    split_h_kernel<<<(n4 + 255) / 256, 256>>>(x, x_h, n4);
    dim3 wgrid(32, 32, 4), wblk(32, 8);
    wsplit4_kernel<<<wgrid, wblk>>>(Wq, Wk, Wv, Wo, wt_h);

    // fused QKV projection -> fp16 (q scaled by 1/8 for attention)
    dim3 gqkv(3 * D_MODEL / 128, ROWS / 128);   // (24, 256)
    gemm_mma_kernel<true><<<gqkv, 256, GEMM_SMEM>>>(
        x_h, wt_h, q_h, k_h, v_h, OSCALE * 0.125f, OSCALE, OSCALE);

    // tensor-core banded attention
    dim3 attn_grid(NH, NCHUNK, BATCH);          // (16, 32, 4)
    attn_mma_kernel<<<attn_grid, 256, ATT_SMEM>>>(q_h, k_h, v_h, att_h);

    // output projection -> fp32
    dim3 go(D_MODEL / 128, ROWS / 128);
    gemm_mma_kernel<false><<<go, 256, GEMM_SMEM>>>(
        att_h, wt_h + 3 * DD, out, out, out, OSCALE, OSCALE, OSCALE);
}

// round 15
// speedup vs baseline: 3.4154x; 1.0160x over previous
#include <cuda_runtime.h>
#include <cuda_bf16.h>
#include <cuda_fp16.h>
#include <cstdint>

#define D_MODEL 1024
#define NH 16
#define HD 64
#define CHUNK 256
#define WIN 64
#define BATCH 4
#define SEQ 8192
#define NCHUNK (SEQ / CHUNK)
#define ROWS (BATCH * SEQ)

#define WSCALE 32.0f
#define OSCALE (1.0f / 32.0f)

// ---------------- scratch (__device__ globals; no allocs allowed) ----------
__device__ __half g_q_h[ROWS * D_MODEL];     // fp16(q/8)
__device__ __half g_k_h[ROWS * D_MODEL];     // fp16(k)
__device__ __half g_v_h[ROWS * D_MODEL];     // fp16(v)
__device__ __half g_x_h[ROWS * D_MODEL];     // fp16(x)
__device__ __half g_att_h[ROWS * D_MODEL];   // fp16(att)
__device__ __half g_wt_h[4 * D_MODEL * D_MODEL];  // fp16(32*W^T), K-major

// ---------------------------------------------------------------------------
// helpers
// ---------------------------------------------------------------------------
__device__ __forceinline__ uint32_t smem_u32(const void* p) {
    uint32_t a;
    asm("{ .reg .u64 t; cvta.to.shared.u64 t, %1; cvt.u32.u64 %0, t; }"
        : "=r"(a) : "l"(p));
    return a;
}
__device__ __forceinline__ void cp_async16(uint32_t dst, const void* src) {
    asm volatile("cp.async.cg.shared.global [%0], [%1], 16;"
                 :: "r"(dst), "l"(src) : "memory");
}
__device__ __forceinline__ void cp_commit() {
    asm volatile("cp.async.commit_group;" ::: "memory");
}
__device__ __forceinline__ void cp_wait1() {
    asm volatile("cp.async.wait_group 1;" ::: "memory");
}
__device__ __forceinline__ void cp_wait0() {
    asm volatile("cp.async.wait_group 0;" ::: "memory");
}
__device__ __forceinline__ void ldsm_x4(uint32_t* r, uint32_t addr) {
    asm volatile("ldmatrix.sync.aligned.m8n8.x4.shared.b16 {%0,%1,%2,%3}, [%4];"
                 : "=r"(r[0]), "=r"(r[1]), "=r"(r[2]), "=r"(r[3]) : "r"(addr));
}
__device__ __forceinline__ void ldsm_x4_t(uint32_t* r, uint32_t addr) {
    asm volatile("ldmatrix.sync.aligned.m8n8.x4.trans.shared.b16 {%0,%1,%2,%3}, [%4];"
                 : "=r"(r[0]), "=r"(r[1]), "=r"(r[2]), "=r"(r[3]) : "r"(addr));
}
__device__ __forceinline__ void mma16816h(float* c, const uint32_t* a, const uint32_t* b) {
    asm volatile(
        "mma.sync.aligned.m16n8k16.row.col.f32.f16.f16.f32 "
        "{%0,%1,%2,%3}, {%4,%5,%6,%7}, {%8,%9}, {%0,%1,%2,%3};"
        : "+f"(c[0]), "+f"(c[1]), "+f"(c[2]), "+f"(c[3])
        : "r"(a[0]), "r"(a[1]), "r"(a[2]), "r"(a[3]), "r"(b[0]), "r"(b[1]));
}

// 128B fp16 rows (64 halfs), 8x 16B chunks, swizzle c' = c ^ (r & 7)
__device__ __forceinline__ uint32_t hsw(uint32_t tile_base, int r, int c) {
    return tile_base + r * 128 + (((c) ^ (r & 7)) << 4);
}

// ---------------------------------------------------------------------------
// conversions
// ---------------------------------------------------------------------------
__global__ __launch_bounds__(256) void split_h_kernel(
    const float* __restrict__ in, __half* __restrict__ out, int n4)
{
    int i = blockIdx.x * blockDim.x + threadIdx.x;
    if (i >= n4) return;
    float4 x = ((const float4*)in)[i];
    __half h[4] = {__float2half(x.x), __float2half(x.y),
                   __float2half(x.z), __float2half(x.w)};
    *(uint2*)(out + 4 * (size_t)i) = *(uint2*)h;
}

__global__ __launch_bounds__(256) void wsplit4_kernel(
    const float* __restrict__ W0, const float* __restrict__ W1,
    const float* __restrict__ W2, const float* __restrict__ W3,
    __half* __restrict__ hT)
{
    __shared__ float tile[32][33];
    const int z = blockIdx.z;
    const float* W = (z == 0) ? W0 : (z == 1) ? W1 : (z == 2) ? W2 : W3;
    const size_t off = (size_t)z * D_MODEL * D_MODEL;
    int bx = blockIdx.x * 32, by = blockIdx.y * 32;
    int tx = threadIdx.x, ty = threadIdx.y;
#pragma unroll
    for (int r = ty; r < 32; r += 8)
        tile[r][tx] = W[(size_t)(by + r) * D_MODEL + bx + tx];
    __syncthreads();
#pragma unroll
    for (int r = ty; r < 32; r += 8) {
        float v = tile[tx][r] * WSCALE;
        hT[off + (size_t)(bx + r) * D_MODEL + by + tx] = __float2half(v);
    }
}

// ---------------------------------------------------------------------------
// Single-pass fp16 GEMM: CTA 128x128, FOUR warps (2m x 2n), warp tile 64x64
// (32 mma : 8 ldsm per k16 = 4:1), BK=64, 3-stage cp.async, 2 CTAs/SM.
// HALF_OUT: fp16 epilogue (QKV path, per-output scale). Else fp32 (O path).
// ---------------------------------------------------------------------------
#define TILE_B 16384
#define STAGE_B (2 * TILE_B)
#define NSTAGE 3
#define GEMM_SMEM (NSTAGE * STAGE_B)  // 98304
#define KIT 16

template <bool HALF_OUT>
__global__ __launch_bounds__(128, 2) void gemm_mma_kernel(
    const __half* __restrict__ A, const __half* __restrict__ B,
    void* __restrict__ C0v, void* __restrict__ C1v, void* __restrict__ C2v,
    float s0, float s1, float s2)
{
    extern __shared__ char smem[];
    const uint32_t sbase = smem_u32(smem);
    const int tid = threadIdx.x;
    const int lane = tid & 31;
    const int wid = tid >> 5;       // 0..3
    const int wm = wid >> 1;        // 0..1
    const int wn = wid & 1;         // 0..1
    const int m0 = blockIdx.y * 128;
    const int nB = blockIdx.x * 128;
    const int w = nB >> 10;
    const int col0 = nB & 1023;
    void* Cv = (w == 0) ? C0v : (w == 1) ? C1v : C2v;
    const float sc = (w == 0) ? s0 : (w == 1) ? s1 : s2;

    auto load_stage = [&](int stage, int k0) {
        uint32_t sb = sbase + stage * STAGE_B;
#pragma unroll
        for (int i = 0; i < 16; i++) {
            int cid = tid + i * 128;       // 0..2047
            int t = cid >> 10;             // 0=A, 1=B
            int e = cid & 1023;
            int r = e >> 3;
            int c = e & 7;
            const __half* s = t ? B : A;
            int row0 = t ? nB : m0;
            const void* g = s + (size_t)(row0 + r) * D_MODEL + k0 + c * 8;
            cp_async16(hsw(sb + t * TILE_B, r, c), g);
        }
    };

    float acc[4][8][4];
#pragma unroll
    for (int i = 0; i < 4; i++)
#pragma unroll
        for (int j = 0; j < 8; j++)
#pragma unroll
            for (int e = 0; e < 4; e++) acc[i][j][e] = 0.f;

    load_stage(0, 0);
    cp_commit();
    load_stage(1, 64);
    cp_commit();

    const int a_r = lane & 15;
    const int a_c = lane >> 4;
    const int b_r = (lane & 7) + ((lane >> 4) << 3);
    const int b_c = (lane >> 3) & 1;

    for (int it = 0; it < KIT; it++) {
        cp_wait1();
        __syncthreads();
        if (it + 2 < KIT) load_stage((it + 2) % NSTAGE, (it + 2) * 64);
        cp_commit();

        const uint32_t sb = sbase + (it % NSTAGE) * STAGE_B;
        const uint32_t tA = sb;
        const uint32_t tB = sb + TILE_B;

#pragma unroll
        for (int ks = 0; ks < 4; ks++) {
            uint32_t a[4][4], bf[8][2];
#pragma unroll
            for (int mt = 0; mt < 4; mt++) {
                int r = wm * 64 + mt * 16 + a_r;
                ldsm_x4(a[mt], hsw(tA, r, ks * 2 + a_c));
            }
#pragma unroll
            for (int np = 0; np < 4; np++) {
                uint32_t t4[4];
                int r = wn * 64 + np * 16 + b_r;
                ldsm_x4(t4, hsw(tB, r, ks * 2 + b_c));
                bf[np * 2][0] = t4[0]; bf[np * 2][1] = t4[1];
                bf[np * 2 + 1][0] = t4[2]; bf[np * 2 + 1][1] = t4[3];
            }
#pragma unroll
            for (int mt = 0; mt < 4; mt++)
#pragma unroll
                for (int nt = 0; nt < 8; nt++)
                    mma16816h(acc[mt][nt], a[mt], bf[nt]);
        }
    }

    const int er = lane >> 2;
    const int ec = (lane & 3) * 2;
#pragma unroll
    for (int mt = 0; mt < 4; mt++) {
#pragma unroll
        for (int nt = 0; nt < 8; nt++) {
            int row = m0 + wm * 64 + mt * 16 + er;
            int col = col0 + wn * 64 + nt * 8 + ec;
            if (HALF_OUT) {
                __half* C = (__half*)Cv;
                __half2 h0 = __floats2half2_rn(acc[mt][nt][0] * sc, acc[mt][nt][1] * sc);
                __half2 h1 = __floats2half2_rn(acc[mt][nt][2] * sc, acc[mt][nt][3] * sc);
                *(__half2*)(C + (size_t)row * D_MODEL + col) = h0;
                *(__half2*)(C + (size_t)(row + 8) * D_MODEL + col) = h1;
            } else {
                float* C = (float*)Cv;
                *(float2*)(C + (size_t)row * D_MODEL + col) =
                    make_float2(acc[mt][nt][0] * sc, acc[mt][nt][1] * sc);
                *(float2*)(C + (size_t)(row + 8) * D_MODEL + col) =
                    make_float2(acc[mt][nt][2] * sc, acc[mt][nt][3] * sc);
            }
        }
    }
}

// ---------------------------------------------------------------------------
// Tensor-core banded attention (unchanged from R13). CTA = (head,chunk,b),
// 8 warps, warp = 32 query rows. Band = 10 n8 tiles per m16. fp16 in/out.
// ---------------------------------------------------------------------------
#define ATT_SMEM (3 * 32768)

__global__ __launch_bounds__(256, 2) void attn_mma_kernel(
    const __half* __restrict__ q, const __half* __restrict__ k,
    const __half* __restrict__ v, __half* __restrict__ o)
{
    extern __shared__ char smem[];
    const uint32_t sb = smem_u32(smem);
    const int tid = threadIdx.x;
    const int lane = tid & 31;
    const int warp = tid >> 5;
    const int h = blockIdx.x, n = blockIdx.y, b = blockIdx.z;
    const size_t base = ((size_t)(b * SEQ + n * CHUNK)) * D_MODEL + h * HD;

    {
        const __half* srcs[3] = {q, k, v};
#pragma unroll
        for (int i = 0; i < 24; i++) {
            int idx = tid + i * 256;
            int t = idx >> 11;
            int e = idx & 2047;
            int r = e >> 3, c = e & 7;
            const void* g = srcs[t] + base + (size_t)r * D_MODEL + c * 8;
            cp_async16(hsw(sb + t * 32768, r, c), g);
        }
        cp_commit();
        cp_wait0();
        __syncthreads();
    }

    const uint32_t sQ = sb, sK = sb + 32768, sV = sb + 65536;
    const int lr = lane >> 2;
    const int lc = lane & 3;

#pragma unroll
    for (int mt = 0; mt < 2; mt++) {
        const int r0 = warp * 32 + mt * 16;

        uint32_t qa[4][4];
#pragma unroll
        for (int kk = 0; kk < 4; kk++)
            ldsm_x4(qa[kk], hsw(sQ, r0 + (lane & 15), kk * 2 + (lane >> 4)));

        const int st = (r0 >> 3) - 8;
        uint32_t pa[5][4];
        float sum0 = 0.f, sum1 = 0.f;

#pragma unroll
        for (int p = 0; p < 5; p++) {
            int t0 = st + 2 * p;
            if (t0 < 0) continue;
            float c0f[4] = {0.f, 0.f, 0.f, 0.f};
            float c1f[4] = {0.f, 0.f, 0.f, 0.f};
#pragma unroll
            for (int kk = 0; kk < 4; kk++) {
                uint32_t r4[4];
                ldsm_x4(r4, hsw(sK, 8 * t0 + (lane & 15), kk * 2 + (lane >> 4)));
                uint32_t b0[2] = {r4[0], r4[2]};
                uint32_t b1[2] = {r4[1], r4[3]};
                mma16816h(c0f, qa[kk], b0);
                mma16816h(c1f, qa[kk], b1);
            }
            const int row0 = r0 + lr, row1 = row0 + 8;
            const int col = 8 * t0 + 2 * lc;
            float e0 = (col     >= row0 - 64 && col     <= row0) ? __expf(c0f[0]) : 0.f;
            float e1 = (col + 1 >= row0 - 64 && col + 1 <= row0) ? __expf(c0f[1]) : 0.f;
            float e2 = (col     >= row1 - 64 && col     <= row1) ? __expf(c0f[2]) : 0.f;
            float e3 = (col + 1 >= row1 - 64 && col + 1 <= row1) ? __expf(c0f[3]) : 0.f;
            float e4 = (col + 8 >= row0 - 64 && col + 8 <= row0) ? __expf(c1f[0]) : 0.f;
            float e5 = (col + 9 >= row0 - 64 && col + 9 <= row0) ? __expf(c1f[1]) : 0.f;
            float e6 = (col + 8 >= row1 - 64 && col + 8 <= row1) ? __expf(c1f[2]) : 0.f;
            float e7 = (col + 9 >= row1 - 64 && col + 9 <= row1) ? __expf(c1f[3]) : 0.f;
            sum0 += e0 + e1 + e4 + e5;
            sum1 += e2 + e3 + e6 + e7;
            __half2 p0 = __floats2half2_rn(e0, e1);
            __half2 p1 = __floats2half2_rn(e2, e3);
            __half2 p2 = __floats2half2_rn(e4, e5);
            __half2 p3 = __floats2half2_rn(e6, e7);
            pa[p][0] = *(uint32_t*)&p0;
            pa[p][1] = *(uint32_t*)&p1;
            pa[p][2] = *(uint32_t*)&p2;
            pa[p][3] = *(uint32_t*)&p3;
        }
        sum0 += __shfl_xor_sync(0xffffffffu, sum0, 1);
        sum0 += __shfl_xor_sync(0xffffffffu, sum0, 2);
        sum1 += __shfl_xor_sync(0xffffffffu, sum1, 1);
        sum1 += __shfl_xor_sync(0xffffffffu, sum1, 2);

        float acc[8][4];
#pragma unroll
        for (int i = 0; i < 8; i++)
#pragma unroll
            for (int e = 0; e < 4; e++) acc[i][e] = 0.f;
#pragma unroll
        for (int p = 0; p < 5; p++) {
            int t0 = st + 2 * p;
            if (t0 < 0) continue;
            int k0 = 8 * t0;
#pragma unroll
            for (int nt2 = 0; nt2 < 4; nt2++) {
                uint32_t r4[4];
                ldsm_x4_t(r4, hsw(sV, k0 + (lane & 15), nt2 * 2 + (lane >> 4)));
                uint32_t b0[2] = {r4[0], r4[1]};
                uint32_t b1[2] = {r4[2], r4[3]};
                mma16816h(acc[2 * nt2], pa[p], b0);
                mma16816h(acc[2 * nt2 + 1], pa[p], b1);
            }
        }
        const float ri0 = 1.f / sum0;
        const float ri1 = 1.f / sum1;
        const int row0 = r0 + lr;
#pragma unroll
        for (int nt = 0; nt < 8; nt++) {
            __half2 h0 = __floats2half2_rn(acc[nt][0] * ri0, acc[nt][1] * ri0);
            __half2 h1 = __floats2half2_rn(acc[nt][2] * ri1, acc[nt][3] * ri1);
            *(__half2*)(o + base + (size_t)row0 * D_MODEL + nt * 8 + 2 * lc) = h0;
            *(__half2*)(o + base + (size_t)(row0 + 8) * D_MODEL + nt * 8 + 2 * lc) = h1;
        }
    }
}

// ---------------------------------------------------------------------------
extern "C" void kernel_launch(void* const* d_in, const int* in_sizes, int n_in,
                              void* d_out, int out_size)
{
    const float* x  = (const float*)d_in[0];
    const float* Wq = (const float*)d_in[1];
    const float* Wk = (const float*)d_in[2];
    const float* Wv = (const float*)d_in[3];
    const float* Wo = (const float*)d_in[4];
    float* out = (float*)d_out;

    __half *q_h, *k_h, *v_h, *x_h, *att_h, *wt_h;
    cudaGetSymbolAddress((void**)&q_h, g_q_h);
    cudaGetSymbolAddress((void**)&k_h, g_k_h);
    cudaGetSymbolAddress((void**)&v_h, g_v_h);
    cudaGetSymbolAddress((void**)&x_h, g_x_h);
    cudaGetSymbolAddress((void**)&att_h, g_att_h);
    cudaGetSymbolAddress((void**)&wt_h, g_wt_h);

    cudaFuncSetAttribute(gemm_mma_kernel<true>,
                         cudaFuncAttributeMaxDynamicSharedMemorySize, GEMM_SMEM);
    cudaFuncSetAttribute(gemm_mma_kernel<false>,
                         cudaFuncAttributeMaxDynamicSharedMemorySize, GEMM_SMEM);
    cudaFuncSetAttribute(attn_mma_kernel,
                         cudaFuncAttributeMaxDynamicSharedMemorySize, ATT_SMEM);

    const size_t DD = (size_t)D_MODEL * D_MODEL;
    const int n4 = ROWS * D_MODEL / 4;

    // conversions
    split_h_kernel<<<(n4 + 255) / 256, 256>>>(x, x_h, n4);
    dim3 wgrid(32, 32, 4), wblk(32, 8);
    wsplit4_kernel<<<wgrid, wblk>>>(Wq, Wk, Wv, Wo, wt_h);

    // fused QKV projection -> fp16 (q scaled by 1/8 for attention)
    dim3 gqkv(3 * D_MODEL / 128, ROWS / 128);   // (24, 256)
    gemm_mma_kernel<true><<<gqkv, 128, GEMM_SMEM>>>(
        x_h, wt_h, q_h, k_h, v_h, OSCALE * 0.125f, OSCALE, OSCALE);

    // tensor-core banded attention
    dim3 attn_grid(NH, NCHUNK, BATCH);          // (16, 32, 4)
    attn_mma_kernel<<<attn_grid, 256, ATT_SMEM>>>(q_h, k_h, v_h, att_h);

    // output projection -> fp32
    dim3 go(D_MODEL / 128, ROWS / 128);
    gemm_mma_kernel<false><<<go, 128, GEMM_SMEM>>>(
        att_h, wt_h + 3 * DD, out, out, out, OSCALE, OSCALE, OSCALE);
}

// round 16
// speedup vs baseline: 3.4889x; 1.0215x over previous
#include <cuda_runtime.h>
#include <cuda_bf16.h>
#include <cuda_fp16.h>
#include <cstdint>

#define D_MODEL 1024
#define NH 16
#define HD 64
#define CHUNK 256
#define WIN 64
#define BATCH 4
#define SEQ 8192
#define NCHUNK (SEQ / CHUNK)
#define ROWS (BATCH * SEQ)

#define WSCALE 32.0f
#define OSCALE (1.0f / 32.0f)

// ---------------- scratch (__device__ globals; no allocs allowed) ----------
__device__ __half g_q_h[ROWS * D_MODEL];     // fp16(q/8)
__device__ __half g_k_h[ROWS * D_MODEL];     // fp16(k)
__device__ __half g_v_h[ROWS * D_MODEL];     // fp16(v)
__device__ __half g_x_h[ROWS * D_MODEL];     // fp16(x)
__device__ __half g_att_h[ROWS * D_MODEL];   // fp16(att)
__device__ __half g_wt_h[4 * D_MODEL * D_MODEL];  // fp16(32*W^T), K-major

// ---------------------------------------------------------------------------
// helpers
// ---------------------------------------------------------------------------
__device__ __forceinline__ uint32_t smem_u32(const void* p) {
    uint32_t a;
    asm("{ .reg .u64 t; cvta.to.shared.u64 t, %1; cvt.u32.u64 %0, t; }"
        : "=r"(a) : "l"(p));
    return a;
}
__device__ __forceinline__ void cp_async16(uint32_t dst, const void* src) {
    asm volatile("cp.async.cg.shared.global [%0], [%1], 16;"
                 :: "r"(dst), "l"(src) : "memory");
}
__device__ __forceinline__ void cp_commit() {
    asm volatile("cp.async.commit_group;" ::: "memory");
}
__device__ __forceinline__ void cp_wait1() {
    asm volatile("cp.async.wait_group 1;" ::: "memory");
}
__device__ __forceinline__ void cp_wait0() {
    asm volatile("cp.async.wait_group 0;" ::: "memory");
}
__device__ __forceinline__ void ldsm_x4(uint32_t* r, uint32_t addr) {
    asm volatile("ldmatrix.sync.aligned.m8n8.x4.shared.b16 {%0,%1,%2,%3}, [%4];"
                 : "=r"(r[0]), "=r"(r[1]), "=r"(r[2]), "=r"(r[3]) : "r"(addr));
}
__device__ __forceinline__ void ldsm_x4_t(uint32_t* r, uint32_t addr) {
    asm volatile("ldmatrix.sync.aligned.m8n8.x4.trans.shared.b16 {%0,%1,%2,%3}, [%4];"
                 : "=r"(r[0]), "=r"(r[1]), "=r"(r[2]), "=r"(r[3]) : "r"(addr));
}
__device__ __forceinline__ void mma16816h(float* c, const uint32_t* a, const uint32_t* b) {
    asm volatile(
        "mma.sync.aligned.m16n8k16.row.col.f32.f16.f16.f32 "
        "{%0,%1,%2,%3}, {%4,%5,%6,%7}, {%8,%9}, {%0,%1,%2,%3};"
        : "+f"(c[0]), "+f"(c[1]), "+f"(c[2]), "+f"(c[3])
        : "r"(a[0]), "r"(a[1]), "r"(a[2]), "r"(a[3]), "r"(b[0]), "r"(b[1]));
}

// 128B fp16 rows (64 halfs), 8x 16B chunks, swizzle c' = c ^ (r & 7)
__device__ __forceinline__ uint32_t hsw(uint32_t tile_base, int r, int c) {
    return tile_base + r * 128 + (((c) ^ (r & 7)) << 4);
}

// ---------------------------------------------------------------------------
// conversions
// ---------------------------------------------------------------------------
__global__ __launch_bounds__(256) void split_h_kernel(
    const float* __restrict__ in, __half* __restrict__ out, int n4)
{
    int i = blockIdx.x * blockDim.x + threadIdx.x;
    if (i >= n4) return;
    float4 x = ((const float4*)in)[i];
    __half h[4] = {__float2half(x.x), __float2half(x.y),
                   __float2half(x.z), __float2half(x.w)};
    *(uint2*)(out + 4 * (size_t)i) = *(uint2*)h;
}

__global__ __launch_bounds__(256) void wsplit4_kernel(
    const float* __restrict__ W0, const float* __restrict__ W1,
    const float* __restrict__ W2, const float* __restrict__ W3,
    __half* __restrict__ hT)
{
    __shared__ float tile[32][33];
    const int z = blockIdx.z;
    const float* W = (z == 0) ? W0 : (z == 1) ? W1 : (z == 2) ? W2 : W3;
    const size_t off = (size_t)z * D_MODEL * D_MODEL;
    int bx = blockIdx.x * 32, by = blockIdx.y * 32;
    int tx = threadIdx.x, ty = threadIdx.y;
#pragma unroll
    for (int r = ty; r < 32; r += 8)
        tile[r][tx] = W[(size_t)(by + r) * D_MODEL + bx + tx];
    __syncthreads();
#pragma unroll
    for (int r = ty; r < 32; r += 8) {
        float v = tile[tx][r] * WSCALE;
        hT[off + (size_t)(bx + r) * D_MODEL + by + tx] = __float2half(v);
    }
}

// ---------------------------------------------------------------------------
// Single-pass fp16 GEMM: CTA 128x128, 4 warps (2m x 2n), warp tile 64x64,
// BK=64, 3-stage cp.async, 2 CTAs/SM, REGISTER-DOUBLE-BUFFERED fragments
// (ldsm for ks+1 overlaps the 32-mma burst of ks).
// HALF_OUT: fp16 epilogue (QKV path, per-output scale). Else fp32 (O path).
// ---------------------------------------------------------------------------
#define TILE_B 16384
#define STAGE_B (2 * TILE_B)
#define NSTAGE 3
#define GEMM_SMEM (NSTAGE * STAGE_B)  // 98304
#define KIT 16

template <bool HALF_OUT>
__global__ __launch_bounds__(128, 2) void gemm_mma_kernel(
    const __half* __restrict__ A, const __half* __restrict__ B,
    void* __restrict__ C0v, void* __restrict__ C1v, void* __restrict__ C2v,
    float s0, float s1, float s2)
{
    extern __shared__ char smem[];
    const uint32_t sbase = smem_u32(smem);
    const int tid = threadIdx.x;
    const int lane = tid & 31;
    const int wid = tid >> 5;       // 0..3
    const int wm = wid >> 1;        // 0..1
    const int wn = wid & 1;         // 0..1
    const int m0 = blockIdx.y * 128;
    const int nB = blockIdx.x * 128;
    const int w = nB >> 10;
    const int col0 = nB & 1023;
    void* Cv = (w == 0) ? C0v : (w == 1) ? C1v : C2v;
    const float sc = (w == 0) ? s0 : (w == 1) ? s1 : s2;

    auto load_stage = [&](int stage, int k0) {
        uint32_t sb = sbase + stage * STAGE_B;
#pragma unroll
        for (int i = 0; i < 16; i++) {
            int cid = tid + i * 128;       // 0..2047
            int t = cid >> 10;             // 0=A, 1=B
            int e = cid & 1023;
            int r = e >> 3;
            int c = e & 7;
            const __half* s = t ? B : A;
            int row0 = t ? nB : m0;
            const void* g = s + (size_t)(row0 + r) * D_MODEL + k0 + c * 8;
            cp_async16(hsw(sb + t * TILE_B, r, c), g);
        }
    };

    float acc[4][8][4];
#pragma unroll
    for (int i = 0; i < 4; i++)
#pragma unroll
        for (int j = 0; j < 8; j++)
#pragma unroll
            for (int e = 0; e < 4; e++) acc[i][j][e] = 0.f;

    load_stage(0, 0);
    cp_commit();
    load_stage(1, 64);
    cp_commit();

    const int a_r = lane & 15;
    const int a_c = lane >> 4;
    const int b_r = (lane & 7) + ((lane >> 4) << 3);
    const int b_c = (lane >> 3) & 1;

    // double-buffered fragments
    uint32_t fa[2][4][4], fb[2][8][2];

    auto load_frags = [&](uint32_t tA, uint32_t tB, int ks, int buf) {
#pragma unroll
        for (int mt = 0; mt < 4; mt++) {
            int r = wm * 64 + mt * 16 + a_r;
            ldsm_x4(fa[buf][mt], hsw(tA, r, ks * 2 + a_c));
        }
#pragma unroll
        for (int np = 0; np < 4; np++) {
            uint32_t t4[4];
            int r = wn * 64 + np * 16 + b_r;
            ldsm_x4(t4, hsw(tB, r, ks * 2 + b_c));
            fb[buf][np * 2][0] = t4[0]; fb[buf][np * 2][1] = t4[1];
            fb[buf][np * 2 + 1][0] = t4[2]; fb[buf][np * 2 + 1][1] = t4[3];
        }
    };

    for (int it = 0; it < KIT; it++) {
        cp_wait1();
        __syncthreads();

        const uint32_t sb = sbase + (it % NSTAGE) * STAGE_B;
        const uint32_t tA = sb;
        const uint32_t tB = sb + TILE_B;

        // restart the fragment pipeline FIRST so the tensor pipe refills ASAP
        load_frags(tA, tB, 0, 0);

        if (it + 2 < KIT) load_stage((it + 2) % NSTAGE, (it + 2) * 64);
        cp_commit();

#pragma unroll
        for (int ks = 0; ks < 4; ks++) {
            if (ks < 3) load_frags(tA, tB, ks + 1, (ks + 1) & 1);
            const int cur = ks & 1;
#pragma unroll
            for (int mt = 0; mt < 4; mt++)
#pragma unroll
                for (int nt = 0; nt < 8; nt++)
                    mma16816h(acc[mt][nt], fa[cur][mt], fb[cur][nt]);
        }
    }

    const int er = lane >> 2;
    const int ec = (lane & 3) * 2;
#pragma unroll
    for (int mt = 0; mt < 4; mt++) {
#pragma unroll
        for (int nt = 0; nt < 8; nt++) {
            int row = m0 + wm * 64 + mt * 16 + er;
            int col = col0 + wn * 64 + nt * 8 + ec;
            if (HALF_OUT) {
                __half* C = (__half*)Cv;
                __half2 h0 = __floats2half2_rn(acc[mt][nt][0] * sc, acc[mt][nt][1] * sc);
                __half2 h1 = __floats2half2_rn(acc[mt][nt][2] * sc, acc[mt][nt][3] * sc);
                *(__half2*)(C + (size_t)row * D_MODEL + col) = h0;
                *(__half2*)(C + (size_t)(row + 8) * D_MODEL + col) = h1;
            } else {
                float* C = (float*)Cv;
                *(float2*)(C + (size_t)row * D_MODEL + col) =
                    make_float2(acc[mt][nt][0] * sc, acc[mt][nt][1] * sc);
                *(float2*)(C + (size_t)(row + 8) * D_MODEL + col) =
                    make_float2(acc[mt][nt][2] * sc, acc[mt][nt][3] * sc);
            }
        }
    }
}

// ---------------------------------------------------------------------------
// Tensor-core banded attention (unchanged from R13). CTA = (head,chunk,b),
// 8 warps, warp = 32 query rows. Band = 10 n8 tiles per m16. fp16 in/out.
// ---------------------------------------------------------------------------
#define ATT_SMEM (3 * 32768)

__global__ __launch_bounds__(256, 2) void attn_mma_kernel(
    const __half* __restrict__ q, const __half* __restrict__ k,
    const __half* __restrict__ v, __half* __restrict__ o)
{
    extern __shared__ char smem[];
    const uint32_t sb = smem_u32(smem);
    const int tid = threadIdx.x;
    const int lane = tid & 31;
    const int warp = tid >> 5;
    const int h = blockIdx.x, n = blockIdx.y, b = blockIdx.z;
    const size_t base = ((size_t)(b * SEQ + n * CHUNK)) * D_MODEL + h * HD;

    {
        const __half* srcs[3] = {q, k, v};
#pragma unroll
        for (int i = 0; i < 24; i++) {
            int idx = tid + i * 256;
            int t = idx >> 11;
            int e = idx & 2047;
            int r = e >> 3, c = e & 7;
            const void* g = srcs[t] + base + (size_t)r * D_MODEL + c * 8;
            cp_async16(hsw(sb + t * 32768, r, c), g);
        }
        cp_commit();
        cp_wait0();
        __syncthreads();
    }

    const uint32_t sQ = sb, sK = sb + 32768, sV = sb + 65536;
    const int lr = lane >> 2;
    const int lc = lane & 3;

#pragma unroll
    for (int mt = 0; mt < 2; mt++) {
        const int r0 = warp * 32 + mt * 16;

        uint32_t qa[4][4];
#pragma unroll
        for (int kk = 0; kk < 4; kk++)
            ldsm_x4(qa[kk], hsw(sQ, r0 + (lane & 15), kk * 2 + (lane >> 4)));

        const int st = (r0 >> 3) - 8;
        uint32_t pa[5][4];
        float sum0 = 0.f, sum1 = 0.f;

#pragma unroll
        for (int p = 0; p < 5; p++) {
            int t0 = st + 2 * p;
            if (t0 < 0) continue;
            float c0f[4] = {0.f, 0.f, 0.f, 0.f};
            float c1f[4] = {0.f, 0.f, 0.f, 0.f};
#pragma unroll
            for (int kk = 0; kk < 4; kk++) {
                uint32_t r4[4];
                ldsm_x4(r4, hsw(sK, 8 * t0 + (lane & 15), kk * 2 + (lane >> 4)));
                uint32_t b0[2] = {r4[0], r4[2]};
                uint32_t b1[2] = {r4[1], r4[3]};
                mma16816h(c0f, qa[kk], b0);
                mma16816h(c1f, qa[kk], b1);
            }
            const int row0 = r0 + lr, row1 = row0 + 8;
            const int col = 8 * t0 + 2 * lc;
            float e0 = (col     >= row0 - 64 && col     <= row0) ? __expf(c0f[0]) : 0.f;
            float e1 = (col + 1 >= row0 - 64 && col + 1 <= row0) ? __expf(c0f[1]) : 0.f;
            float e2 = (col     >= row1 - 64 && col     <= row1) ? __expf(c0f[2]) : 0.f;
            float e3 = (col + 1 >= row1 - 64 && col + 1 <= row1) ? __expf(c0f[3]) : 0.f;
            float e4 = (col + 8 >= row0 - 64 && col + 8 <= row0) ? __expf(c1f[0]) : 0.f;
            float e5 = (col + 9 >= row0 - 64 && col + 9 <= row0) ? __expf(c1f[1]) : 0.f;
            float e6 = (col + 8 >= row1 - 64 && col + 8 <= row1) ? __expf(c1f[2]) : 0.f;
            float e7 = (col + 9 >= row1 - 64 && col + 9 <= row1) ? __expf(c1f[3]) : 0.f;
            sum0 += e0 + e1 + e4 + e5;
            sum1 += e2 + e3 + e6 + e7;
            __half2 p0 = __floats2half2_rn(e0, e1);
            __half2 p1 = __floats2half2_rn(e2, e3);
            __half2 p2 = __floats2half2_rn(e4, e5);
            __half2 p3 = __floats2half2_rn(e6, e7);
            pa[p][0] = *(uint32_t*)&p0;
            pa[p][1] = *(uint32_t*)&p1;
            pa[p][2] = *(uint32_t*)&p2;
            pa[p][3] = *(uint32_t*)&p3;
        }
        sum0 += __shfl_xor_sync(0xffffffffu, sum0, 1);
        sum0 += __shfl_xor_sync(0xffffffffu, sum0, 2);
        sum1 += __shfl_xor_sync(0xffffffffu, sum1, 1);
        sum1 += __shfl_xor_sync(0xffffffffu, sum1, 2);

        float acc[8][4];
#pragma unroll
        for (int i = 0; i < 8; i++)
#pragma unroll
            for (int e = 0; e < 4; e++) acc[i][e] = 0.f;
#pragma unroll
        for (int p = 0; p < 5; p++) {
            int t0 = st + 2 * p;
            if (t0 < 0) continue;
            int k0 = 8 * t0;
#pragma unroll
            for (int nt2 = 0; nt2 < 4; nt2++) {
                uint32_t r4[4];
                ldsm_x4_t(r4, hsw(sV, k0 + (lane & 15), nt2 * 2 + (lane >> 4)));
                uint32_t b0[2] = {r4[0], r4[1]};
                uint32_t b1[2] = {r4[2], r4[3]};
                mma16816h(acc[2 * nt2], pa[p], b0);
                mma16816h(acc[2 * nt2 + 1], pa[p], b1);
            }
        }
        const float ri0 = 1.f / sum0;
        const float ri1 = 1.f / sum1;
        const int row0 = r0 + lr;
#pragma unroll
        for (int nt = 0; nt < 8; nt++) {
            __half2 h0 = __floats2half2_rn(acc[nt][0] * ri0, acc[nt][1] * ri0);
            __half2 h1 = __floats2half2_rn(acc[nt][2] * ri1, acc[nt][3] * ri1);
            *(__half2*)(o + base + (size_t)row0 * D_MODEL + nt * 8 + 2 * lc) = h0;
            *(__half2*)(o + base + (size_t)(row0 + 8) * D_MODEL + nt * 8 + 2 * lc) = h1;
        }
    }
}

// ---------------------------------------------------------------------------
extern "C" void kernel_launch(void* const* d_in, const int* in_sizes, int n_in,
                              void* d_out, int out_size)
{
    const float* x  = (const float*)d_in[0];
    const float* Wq = (const float*)d_in[1];
    const float* Wk = (const float*)d_in[2];
    const float* Wv = (const float*)d_in[3];
    const float* Wo = (const float*)d_in[4];
    float* out = (float*)d_out;

    __half *q_h, *k_h, *v_h, *x_h, *att_h, *wt_h;
    cudaGetSymbolAddress((void**)&q_h, g_q_h);
    cudaGetSymbolAddress((void**)&k_h, g_k_h);
    cudaGetSymbolAddress((void**)&v_h, g_v_h);
    cudaGetSymbolAddress((void**)&x_h, g_x_h);
    cudaGetSymbolAddress((void**)&att_h, g_att_h);
    cudaGetSymbolAddress((void**)&wt_h, g_wt_h);

    cudaFuncSetAttribute(gemm_mma_kernel<true>,
                         cudaFuncAttributeMaxDynamicSharedMemorySize, GEMM_SMEM);
    cudaFuncSetAttribute(gemm_mma_kernel<false>,
                         cudaFuncAttributeMaxDynamicSharedMemorySize, GEMM_SMEM);
    cudaFuncSetAttribute(attn_mma_kernel,
                         cudaFuncAttributeMaxDynamicSharedMemorySize, ATT_SMEM);

    const size_t DD = (size_t)D_MODEL * D_MODEL;
    const int n4 = ROWS * D_MODEL / 4;

    // conversions
    split_h_kernel<<<(n4 + 255) / 256, 256>>>(x, x_h, n4);
    dim3 wgrid(32, 32, 4), wblk(32, 8);
    wsplit4_kernel<<<wgrid, wblk>>>(Wq, Wk, Wv, Wo, wt_h);

    // fused QKV projection -> fp16 (q scaled by 1/8 for attention)
    dim3 gqkv(3 * D_MODEL / 128, ROWS / 128);   // (24, 256)
    gemm_mma_kernel<true><<<gqkv, 128, GEMM_SMEM>>>(
        x_h, wt_h, q_h, k_h, v_h, OSCALE * 0.125f, OSCALE, OSCALE);

    // tensor-core banded attention
    dim3 attn_grid(NH, NCHUNK, BATCH);          // (16, 32, 4)
    attn_mma_kernel<<<attn_grid, 256, ATT_SMEM>>>(q_h, k_h, v_h, att_h);

    // output projection -> fp32
    dim3 go(D_MODEL / 128, ROWS / 128);
    gemm_mma_kernel<false><<<go, 128, GEMM_SMEM>>>(
        att_h, wt_h + 3 * DD, out, out, out, OSCALE, OSCALE, OSCALE);
}